// round 5
// baseline (speedup 1.0000x reference)
#include <cuda_runtime.h>

#define B_  4
#define S_  2048
#define D_  1024
#define H_  16
#define DK_ 64

// Scratch (no cudaMalloc allowed; __device__ globals are the workaround).
__device__ float g_Q[(size_t)B_ * S_ * D_];
__device__ float g_K[(size_t)B_ * S_ * D_];
__device__ float g_V[(size_t)B_ * S_ * D_];
__device__ float g_A[(size_t)B_ * S_ * D_];

// ---------------------------------------------------------------------------
// GEMM: C[M,N] = A[M,K] * B[N,K]^T  (unchanged, known-good, ~450us each)
// ---------------------------------------------------------------------------
__global__ void __launch_bounds__(256)
gemm_atb_kernel(const float* __restrict__ A, const float* __restrict__ Bm,
                float* __restrict__ C, int M, int N, int Kd)
{
    __shared__ float As[16][132];
    __shared__ float Bs[16][132];

    const int tid = threadIdx.x;
    const int m0  = blockIdx.y * 128;
    const int n0  = blockIdx.x * 128;
    const int tx  = tid & 15;
    const int ty  = tid >> 4;

    float acc[8][8];
    #pragma unroll
    for (int i = 0; i < 8; i++)
        #pragma unroll
        for (int j = 0; j < 8; j++) acc[i][j] = 0.f;

    for (int k0 = 0; k0 < Kd; k0 += 16) {
        #pragma unroll
        for (int i = 0; i < 2; i++) {
            int idx = tid + i * 256;
            int row = idx >> 2;
            int kc  = (idx & 3) << 2;
            float4 va = *reinterpret_cast<const float4*>(
                A + (size_t)(m0 + row) * Kd + k0 + kc);
            As[kc + 0][row] = va.x; As[kc + 1][row] = va.y;
            As[kc + 2][row] = va.z; As[kc + 3][row] = va.w;
            float4 vb = *reinterpret_cast<const float4*>(
                Bm + (size_t)(n0 + row) * Kd + k0 + kc);
            Bs[kc + 0][row] = vb.x; Bs[kc + 1][row] = vb.y;
            Bs[kc + 2][row] = vb.z; Bs[kc + 3][row] = vb.w;
        }
        __syncthreads();

        #pragma unroll
        for (int kk = 0; kk < 16; kk++) {
            float4 a0 = *reinterpret_cast<const float4*>(&As[kk][ty * 8]);
            float4 a1 = *reinterpret_cast<const float4*>(&As[kk][ty * 8 + 4]);
            float4 b0 = *reinterpret_cast<const float4*>(&Bs[kk][tx * 8]);
            float4 b1 = *reinterpret_cast<const float4*>(&Bs[kk][tx * 8 + 4]);
            float a[8] = {a0.x, a0.y, a0.z, a0.w, a1.x, a1.y, a1.z, a1.w};
            float b[8] = {b0.x, b0.y, b0.z, b0.w, b1.x, b1.y, b1.z, b1.w};
            #pragma unroll
            for (int i = 0; i < 8; i++)
                #pragma unroll
                for (int j = 0; j < 8; j++)
                    acc[i][j] = fmaf(a[i], b[j], acc[i][j]);
        }
        __syncthreads();
    }

    #pragma unroll
    for (int i = 0; i < 8; i++) {
        float* cp = C + (size_t)(m0 + ty * 8 + i) * N + n0 + tx * 8;
        *reinterpret_cast<float4*>(cp) =
            make_float4(acc[i][0], acc[i][1], acc[i][2], acc[i][3]);
        *reinterpret_cast<float4*>(cp + 4) =
            make_float4(acc[i][4], acc[i][5], acc[i][6], acc[i][7]);
    }
}

// Fast exp on the FMA pipe: e^x = 2^(x*log2e), round-to-int via magic number,
// degree-5 poly for 2^f on [-0.5,0.5] (rel err ~2e-6). No MUFU.
__device__ __forceinline__ float fexp(float x)
{
    float t = fmaxf(x * 1.4426950408889634f, -126.0f);
    float z = t + 12582912.0f;               // 1.5 * 2^23
    int  ei = __float_as_int(z) - 0x4B400000;
    float f = t - (z - 12582912.0f);         // f in [-0.5, 0.5]
    float p = fmaf(0.0013333558f, f, 0.0096181291f);
    p = fmaf(p, f, 0.0555041087f);
    p = fmaf(p, f, 0.2402265069f);
    p = fmaf(p, f, 0.6931471806f);
    p = fmaf(p, f, 1.0f);
    return __int_as_float(__float_as_int(p) + (ei << 23));
}

__device__ __forceinline__ void fma4(float4& a, float s, const float4& v)
{
    a.x = fmaf(s, v.x, a.x); a.y = fmaf(s, v.y, a.y);
    a.z = fmaf(s, v.z, a.z); a.w = fmaf(s, v.w, a.w);
}

// ---------------------------------------------------------------------------
// Register-tiled flash attention.
// CTA: 128 threads, 128-query tile, 64-key tiles, 32 tiles over S=2048.
// Thread (qx = tid>>3 in 0..15, ky = tid&7):
//   S phase : 8x8 score microtile, rows q = 16*i+qx, keys k = 8*j+ky
//             (interleaved so LDS bank groups vary with qx/ky -> <=2-way)
//   softmax : row reduce over the 8 ky-lanes via __shfl_xor (same warp)
//   PV phase: thread owns output slice d = ky*8..+7 for its 8 q rows,
//             P read back from smem (float4 over keys).
// Smem (dynamic, 104 KB): Qs[128][68], Ks[64][72], Vs[64][72], Ps[128][68].
// ---------------------------------------------------------------------------
#define QS_ST 68
#define KS_ST 72
#define PS_ST 68
#define SM_QS 0
#define SM_KS (128 * QS_ST)                    // 8704
#define SM_VS (SM_KS + 64 * KS_ST)             // 13312
#define SM_PS (SM_VS + 64 * KS_ST)             // 17920
#define SM_TOT (SM_PS + 128 * PS_ST)           // 26624 floats = 106496 B

__global__ void __launch_bounds__(128)
attn_kernel(const float* __restrict__ Q, const float* __restrict__ Kt,
            const float* __restrict__ Vt, const int* __restrict__ mask,
            float* __restrict__ O)
{
    extern __shared__ float sm[];
    float* Qs = sm + SM_QS;
    float* Ks = sm + SM_KS;
    float* Vs = sm + SM_VS;
    float* Ps = sm + SM_PS;

    const int tid = threadIdx.x;
    const int qx  = tid >> 3;              // 0..15
    const int ky  = tid & 7;               // 0..7
    const int b   = blockIdx.y >> 4;
    const int h   = blockIdx.y & 15;
    const int q0  = blockIdx.x * 128;

    // ---- stage Q tile [128 x 64] into smem (once) ----
    #pragma unroll
    for (int i = 0; i < 16; i++) {
        int idx = tid + i * 128;           // 0..2047
        int r = idx >> 4, c = idx & 15;
        *reinterpret_cast<float4*>(&Qs[r * QS_ST + c * 4]) =
            *reinterpret_cast<const float4*>(
                Q + ((size_t)b * S_ + q0 + r) * D_ + h * DK_ + c * 4);
    }

    float4 o0[8], o1[8];
    float mrun[8], lrun[8];
    #pragma unroll
    for (int i = 0; i < 8; i++) {
        o0[i] = make_float4(0.f, 0.f, 0.f, 0.f);
        o1[i] = make_float4(0.f, 0.f, 0.f, 0.f);
        mrun[i] = -1e30f; lrun[i] = 0.f;
    }

    for (int kt = 0; kt < S_; kt += 64) {
        __syncthreads();   // prev tile's S/PV reads of Ks/Vs + PV reads of Ps done
        // ---- stage K,V tiles [64 x 64] ----
        #pragma unroll
        for (int i = 0; i < 8; i++) {
            int idx = tid + i * 128;       // 0..1023
            int r = idx >> 4, c = idx & 15;
            size_t g = ((size_t)b * S_ + kt + r) * D_ + h * DK_ + c * 4;
            *reinterpret_cast<float4*>(&Ks[r * KS_ST + c * 4]) =
                *reinterpret_cast<const float4*>(Kt + g);
            *reinterpret_cast<float4*>(&Vs[r * KS_ST + c * 4]) =
                *reinterpret_cast<const float4*>(Vt + g);
        }
        __syncthreads();

        // ---- S = Q K^T : 8x8 microtile ----
        float s[8][8];
        #pragma unroll
        for (int i = 0; i < 8; i++)
            #pragma unroll
            for (int j = 0; j < 8; j++) s[i][j] = 0.f;

        #pragma unroll
        for (int d4 = 0; d4 < 16; d4++) {
            float4 qv[8], kv[8];
            #pragma unroll
            for (int i = 0; i < 8; i++)
                qv[i] = *reinterpret_cast<const float4*>(
                    &Qs[(i * 16 + qx) * QS_ST + d4 * 4]);
            #pragma unroll
            for (int j = 0; j < 8; j++)
                kv[j] = *reinterpret_cast<const float4*>(
                    &Ks[(j * 8 + ky) * KS_ST + d4 * 4]);
            #pragma unroll
            for (int i = 0; i < 8; i++)
                #pragma unroll
                for (int j = 0; j < 8; j++) {
                    float acc = s[i][j];
                    acc = fmaf(qv[i].x, kv[j].x, acc);
                    acc = fmaf(qv[i].y, kv[j].y, acc);
                    acc = fmaf(qv[i].z, kv[j].z, acc);
                    acc = fmaf(qv[i].w, kv[j].w, acc);
                    s[i][j] = acc;
                }
        }

        // ---- scale + mask + online softmax; write P to smem ----
        #pragma unroll
        for (int i = 0; i < 8; i++) {
            const int qrow = q0 + i * 16 + qx;
            const int* mp = mask + ((size_t)b * S_ + qrow) * S_ + kt;
            float rm = -1e30f;
            #pragma unroll
            for (int j = 0; j < 8; j++) {
                float sv = s[i][j] * 0.125f;            // 1/sqrt(64)
                if (mp[j * 8 + ky] == 0) sv = -1e9f;
                s[i][j] = sv;
                rm = fmaxf(rm, sv);
            }
            rm = fmaxf(rm, __shfl_xor_sync(0xffffffffu, rm, 1));
            rm = fmaxf(rm, __shfl_xor_sync(0xffffffffu, rm, 2));
            rm = fmaxf(rm, __shfl_xor_sync(0xffffffffu, rm, 4));

            float mnew = fmaxf(mrun[i], rm);
            float corr = fexp(mrun[i] - mnew);
            float lr   = lrun[i] * corr;
            o0[i].x *= corr; o0[i].y *= corr; o0[i].z *= corr; o0[i].w *= corr;
            o1[i].x *= corr; o1[i].y *= corr; o1[i].z *= corr; o1[i].w *= corr;

            float sum = 0.f;
            #pragma unroll
            for (int j = 0; j < 8; j++) {
                float p = fexp(s[i][j] - mnew);
                sum += p;
                Ps[(i * 16 + qx) * PS_ST + j * 8 + ky] = p;
            }
            sum += __shfl_xor_sync(0xffffffffu, sum, 1);
            sum += __shfl_xor_sync(0xffffffffu, sum, 2);
            sum += __shfl_xor_sync(0xffffffffu, sum, 4);

            lrun[i] = lr + sum;
            mrun[i] = mnew;
        }
        __syncthreads();   // Ps visible to all warps

        // ---- O += P V : thread covers d slice ky*8..+7 ----
        #pragma unroll
        for (int k4 = 0; k4 < 64; k4 += 4) {
            float4 pa[8];
            #pragma unroll
            for (int i = 0; i < 8; i++)
                pa[i] = *reinterpret_cast<const float4*>(
                    &Ps[(i * 16 + qx) * PS_ST + k4]);
            float4 va[4], vb[4];
            #pragma unroll
            for (int t = 0; t < 4; t++) {
                va[t] = *reinterpret_cast<const float4*>(
                    &Vs[(k4 + t) * KS_ST + ky * 8]);
                vb[t] = *reinterpret_cast<const float4*>(
                    &Vs[(k4 + t) * KS_ST + ky * 8 + 4]);
            }
            #pragma unroll
            for (int i = 0; i < 8; i++) {
                fma4(o0[i], pa[i].x, va[0]); fma4(o1[i], pa[i].x, vb[0]);
                fma4(o0[i], pa[i].y, va[1]); fma4(o1[i], pa[i].y, vb[1]);
                fma4(o0[i], pa[i].z, va[2]); fma4(o1[i], pa[i].z, vb[2]);
                fma4(o0[i], pa[i].w, va[3]); fma4(o1[i], pa[i].w, vb[3]);
            }
        }
    }

    // ---- finalize ----
    #pragma unroll
    for (int i = 0; i < 8; i++) {
        float inv = 1.f / lrun[i];
        float* op = O + ((size_t)b * S_ + q0 + i * 16 + qx) * D_ + h * DK_ + ky * 8;
        *reinterpret_cast<float4*>(op) =
            make_float4(o0[i].x * inv, o0[i].y * inv, o0[i].z * inv, o0[i].w * inv);
        *reinterpret_cast<float4*>(op + 4) =
            make_float4(o1[i].x * inv, o1[i].y * inv, o1[i].z * inv, o1[i].w * inv);
    }
}

// ---------------------------------------------------------------------------
// Launch: 5 kernels, graph-capturable, no allocations / syncs.
// ---------------------------------------------------------------------------
extern "C" void kernel_launch(void* const* d_in, const int* in_sizes, int n_in,
                              void* d_out, int out_size)
{
    const float* q    = (const float*)d_in[0];
    const float* k    = (const float*)d_in[1];
    const float* v    = (const float*)d_in[2];
    const int*   mask = (const int*)  d_in[3];
    const float* w_q  = (const float*)d_in[4];
    const float* w_k  = (const float*)d_in[5];
    const float* w_v  = (const float*)d_in[6];
    const float* w_o  = (const float*)d_in[7];
    float* out = (float*)d_out;

    float *gq, *gk, *gv, *ga;
    cudaGetSymbolAddress((void**)&gq, g_Q);
    cudaGetSymbolAddress((void**)&gk, g_K);
    cudaGetSymbolAddress((void**)&gv, g_V);
    cudaGetSymbolAddress((void**)&ga, g_A);

    const int M = B_ * S_;                 // 8192
    dim3 gemm_grid(D_ / 128, M / 128);     // (8, 64)

    gemm_atb_kernel<<<gemm_grid, 256>>>(q, w_q, gq, M, D_, D_);
    gemm_atb_kernel<<<gemm_grid, 256>>>(k, w_k, gk, M, D_, D_);
    gemm_atb_kernel<<<gemm_grid, 256>>>(v, w_v, gv, M, D_, D_);

    const int attn_smem = SM_TOT * (int)sizeof(float);   // 106496 B
    cudaFuncSetAttribute(attn_kernel,
                         cudaFuncAttributeMaxDynamicSharedMemorySize, attn_smem);
    dim3 attn_grid(S_ / 128, B_ * H_);     // (16, 64)
    attn_kernel<<<attn_grid, 128, attn_smem>>>(gq, gk, gv, mask, ga);

    gemm_atb_kernel<<<gemm_grid, 256>>>(ga, w_o, out, M, D_, D_);
}

// round 7
// speedup vs baseline: 1.5545x; 1.5545x over previous
#include <cuda_runtime.h>

#define B_  4
#define S_  2048
#define D_  1024
#define H_  16
#define DK_ 64

// Scratch (no cudaMalloc allowed; __device__ globals are the workaround).
__device__ float g_Q[(size_t)B_ * S_ * D_];
__device__ float g_K[(size_t)B_ * S_ * D_];
__device__ float g_V[(size_t)B_ * S_ * D_];
__device__ float g_A[(size_t)B_ * S_ * D_];

// ---------------------------------------------------------------------------
// GEMM: C[M,N] = A[M,K] * B[N,K]^T  (unchanged, known-good, ~450us each)
// ---------------------------------------------------------------------------
__global__ void __launch_bounds__(256)
gemm_atb_kernel(const float* __restrict__ A, const float* __restrict__ Bm,
                float* __restrict__ C, int M, int N, int Kd)
{
    __shared__ float As[16][132];
    __shared__ float Bs[16][132];

    const int tid = threadIdx.x;
    const int m0  = blockIdx.y * 128;
    const int n0  = blockIdx.x * 128;
    const int tx  = tid & 15;
    const int ty  = tid >> 4;

    float acc[8][8];
    #pragma unroll
    for (int i = 0; i < 8; i++)
        #pragma unroll
        for (int j = 0; j < 8; j++) acc[i][j] = 0.f;

    for (int k0 = 0; k0 < Kd; k0 += 16) {
        #pragma unroll
        for (int i = 0; i < 2; i++) {
            int idx = tid + i * 256;
            int row = idx >> 2;
            int kc  = (idx & 3) << 2;
            float4 va = *reinterpret_cast<const float4*>(
                A + (size_t)(m0 + row) * Kd + k0 + kc);
            As[kc + 0][row] = va.x; As[kc + 1][row] = va.y;
            As[kc + 2][row] = va.z; As[kc + 3][row] = va.w;
            float4 vb = *reinterpret_cast<const float4*>(
                Bm + (size_t)(n0 + row) * Kd + k0 + kc);
            Bs[kc + 0][row] = vb.x; Bs[kc + 1][row] = vb.y;
            Bs[kc + 2][row] = vb.z; Bs[kc + 3][row] = vb.w;
        }
        __syncthreads();

        #pragma unroll
        for (int kk = 0; kk < 16; kk++) {
            float4 a0 = *reinterpret_cast<const float4*>(&As[kk][ty * 8]);
            float4 a1 = *reinterpret_cast<const float4*>(&As[kk][ty * 8 + 4]);
            float4 b0 = *reinterpret_cast<const float4*>(&Bs[kk][tx * 8]);
            float4 b1 = *reinterpret_cast<const float4*>(&Bs[kk][tx * 8 + 4]);
            float a[8] = {a0.x, a0.y, a0.z, a0.w, a1.x, a1.y, a1.z, a1.w};
            float b[8] = {b0.x, b0.y, b0.z, b0.w, b1.x, b1.y, b1.z, b1.w};
            #pragma unroll
            for (int i = 0; i < 8; i++)
                #pragma unroll
                for (int j = 0; j < 8; j++)
                    acc[i][j] = fmaf(a[i], b[j], acc[i][j]);
        }
        __syncthreads();
    }

    #pragma unroll
    for (int i = 0; i < 8; i++) {
        float* cp = C + (size_t)(m0 + ty * 8 + i) * N + n0 + tx * 8;
        *reinterpret_cast<float4*>(cp) =
            make_float4(acc[i][0], acc[i][1], acc[i][2], acc[i][3]);
        *reinterpret_cast<float4*>(cp + 4) =
            make_float4(acc[i][4], acc[i][5], acc[i][6], acc[i][7]);
    }
}

// Fast exp on the FMA pipe (no MUFU): 2^x range reduction + deg-5 poly.
__device__ __forceinline__ float fexp(float x)
{
    float t = fmaxf(x * 1.4426950408889634f, -126.0f);
    float z = t + 12582912.0f;               // 1.5 * 2^23
    int  ei = __float_as_int(z) - 0x4B400000;
    float f = t - (z - 12582912.0f);         // f in [-0.5, 0.5]
    float p = fmaf(0.0013333558f, f, 0.0096181291f);
    p = fmaf(p, f, 0.0555041087f);
    p = fmaf(p, f, 0.2402265069f);
    p = fmaf(p, f, 0.6931471806f);
    p = fmaf(p, f, 1.0f);
    return __int_as_float(__float_as_int(p) + (ei << 23));
}

__device__ __forceinline__ void fma4(float4& a, float s, const float4& v)
{
    a.x = fmaf(s, v.x, a.x); a.y = fmaf(s, v.y, a.y);
    a.z = fmaf(s, v.z, a.z); a.w = fmaf(s, v.w, a.w);
}

// ---------------------------------------------------------------------------
// Register-tiled flash attention, v2: balanced regs vs smem traffic.
// CTA: 256 threads, 128-query tile, 64-key tiles.
// Thread (qx = tid>>3 in 0..31, ky = tid&7):
//   S phase : 4x8 microtile, rows q = 32*i+qx, keys k = 8*j+ky
//   PV phase: thread owns d slice ky*8..+7 for its 4 q rows
// Regs capped at 128 via __launch_bounds__(256,2) -> 16 warps/SM.
// Strides: Qs 68 (qx banks {0,4,8,12} conflict-free), Ks/Vs 76 (ky*76 mod 32
// covers 8 distinct bank groups -> conflict-free kv), Ps 72 (qx*72 mod 32 =
// {0,8,16,24}, ky spans 8 -> disjoint, conflict-free).
// Smem: 110592 B/CTA, 2 CTAs = 221 KB <= 227 KB.
// ---------------------------------------------------------------------------
#define QS_ST 68
#define KS_ST 76
#define PS_ST 72
#define SM_KS (128 * QS_ST)                    // 8704
#define SM_VS (SM_KS + 64 * KS_ST)             // 13568
#define SM_PS (SM_VS + 64 * KS_ST)             // 18432
#define SM_TOT (SM_PS + 128 * PS_ST)           // 27648 floats = 110592 B

__global__ void __launch_bounds__(256, 2)
attn_kernel(const float* __restrict__ Q, const float* __restrict__ Kt,
            const float* __restrict__ Vt, const int* __restrict__ mask,
            float* __restrict__ O)
{
    extern __shared__ float sm[];
    float* Qs = sm;
    float* Ks = sm + SM_KS;
    float* Vs = sm + SM_VS;
    float* Ps = sm + SM_PS;

    const int tid = threadIdx.x;
    const int qx  = tid >> 3;              // 0..31
    const int ky  = tid & 7;               // 0..7
    const int b   = blockIdx.y >> 4;
    const int h   = blockIdx.y & 15;
    const int q0  = blockIdx.x * 128;

    // ---- stage Q tile [128 x 64] (once): 2048 float4 / 256 thr = 8 each ----
    #pragma unroll
    for (int i = 0; i < 8; i++) {
        int idx = tid + i * 256;           // 0..2047
        int r = idx >> 4, c = idx & 15;
        *reinterpret_cast<float4*>(&Qs[r * QS_ST + c * 4]) =
            *reinterpret_cast<const float4*>(
                Q + ((size_t)b * S_ + q0 + r) * D_ + h * DK_ + c * 4);
    }

    float4 o[4][2];
    float mrun[4], lrun[4];
    #pragma unroll
    for (int i = 0; i < 4; i++) {
        o[i][0] = make_float4(0.f, 0.f, 0.f, 0.f);
        o[i][1] = make_float4(0.f, 0.f, 0.f, 0.f);
        mrun[i] = -1e30f; lrun[i] = 0.f;
    }

    for (int kt = 0; kt < S_; kt += 64) {
        __syncthreads();   // prior tile's reads of Ks/Vs/Ps complete
        // ---- stage K,V tiles [64 x 64]: 1024 float4 / 256 thr = 4 each ----
        #pragma unroll
        for (int i = 0; i < 4; i++) {
            int idx = tid + i * 256;       // 0..1023
            int r = idx >> 4, c = idx & 15;
            size_t g = ((size_t)b * S_ + kt + r) * D_ + h * DK_ + c * 4;
            *reinterpret_cast<float4*>(&Ks[r * KS_ST + c * 4]) =
                *reinterpret_cast<const float4*>(Kt + g);
            *reinterpret_cast<float4*>(&Vs[r * KS_ST + c * 4]) =
                *reinterpret_cast<const float4*>(Vt + g);
        }
        __syncthreads();

        // ---- S = Q K^T : 4x8 microtile ----
        float s[4][8];
        #pragma unroll
        for (int i = 0; i < 4; i++)
            #pragma unroll
            for (int j = 0; j < 8; j++) s[i][j] = 0.f;

        #pragma unroll
        for (int d4 = 0; d4 < 16; d4++) {
            float4 kv[8];
            #pragma unroll
            for (int j = 0; j < 8; j++)
                kv[j] = *reinterpret_cast<const float4*>(
                    &Ks[(j * 8 + ky) * KS_ST + d4 * 4]);
            #pragma unroll
            for (int i = 0; i < 4; i++) {
                float4 qv = *reinterpret_cast<const float4*>(
                    &Qs[(i * 32 + qx) * QS_ST + d4 * 4]);
                #pragma unroll
                for (int j = 0; j < 8; j++) {
                    float acc = s[i][j];
                    acc = fmaf(qv.x, kv[j].x, acc);
                    acc = fmaf(qv.y, kv[j].y, acc);
                    acc = fmaf(qv.z, kv[j].z, acc);
                    acc = fmaf(qv.w, kv[j].w, acc);
                    s[i][j] = acc;
                }
            }
        }

        // ---- scale + mask + online softmax; write P to smem ----
        #pragma unroll
        for (int i = 0; i < 4; i++) {
            const int qrow = q0 + i * 32 + qx;
            const int* mp = mask + ((size_t)b * S_ + qrow) * S_ + kt;
            float rm = -1e30f;
            #pragma unroll
            for (int j = 0; j < 8; j++) {
                float sv = s[i][j] * 0.125f;            // 1/sqrt(64)
                if (mp[j * 8 + ky] == 0) sv = -1e9f;
                s[i][j] = sv;
                rm = fmaxf(rm, sv);
            }
            rm = fmaxf(rm, __shfl_xor_sync(0xffffffffu, rm, 1));
            rm = fmaxf(rm, __shfl_xor_sync(0xffffffffu, rm, 2));
            rm = fmaxf(rm, __shfl_xor_sync(0xffffffffu, rm, 4));

            float mnew = fmaxf(mrun[i], rm);
            float corr = fexp(mrun[i] - mnew);
            float lr   = lrun[i] * corr;
            o[i][0].x *= corr; o[i][0].y *= corr;
            o[i][0].z *= corr; o[i][0].w *= corr;
            o[i][1].x *= corr; o[i][1].y *= corr;
            o[i][1].z *= corr; o[i][1].w *= corr;

            float sum = 0.f;
            #pragma unroll
            for (int j = 0; j < 8; j++) {
                float p = fexp(s[i][j] - mnew);
                sum += p;
                Ps[(i * 32 + qx) * PS_ST + j * 8 + ky] = p;
            }
            sum += __shfl_xor_sync(0xffffffffu, sum, 1);
            sum += __shfl_xor_sync(0xffffffffu, sum, 2);
            sum += __shfl_xor_sync(0xffffffffu, sum, 4);

            lrun[i] = lr + sum;
            mrun[i] = mnew;
        }
        __syncthreads();   // Ps visible to all warps

        // ---- O += P V : thread covers d slice ky*8..+7, 4 q rows ----
        #pragma unroll
        for (int k4 = 0; k4 < 64; k4 += 4) {
            float4 pa[4];
            #pragma unroll
            for (int i = 0; i < 4; i++)
                pa[i] = *reinterpret_cast<const float4*>(
                    &Ps[(i * 32 + qx) * PS_ST + k4]);
            float4 va[4], vb[4];
            #pragma unroll
            for (int t = 0; t < 4; t++) {
                va[t] = *reinterpret_cast<const float4*>(
                    &Vs[(k4 + t) * KS_ST + ky * 8]);
                vb[t] = *reinterpret_cast<const float4*>(
                    &Vs[(k4 + t) * KS_ST + ky * 8 + 4]);
            }
            #pragma unroll
            for (int i = 0; i < 4; i++) {
                fma4(o[i][0], pa[i].x, va[0]); fma4(o[i][1], pa[i].x, vb[0]);
                fma4(o[i][0], pa[i].y, va[1]); fma4(o[i][1], pa[i].y, vb[1]);
                fma4(o[i][0], pa[i].z, va[2]); fma4(o[i][1], pa[i].z, vb[2]);
                fma4(o[i][0], pa[i].w, va[3]); fma4(o[i][1], pa[i].w, vb[3]);
            }
        }
    }

    // ---- finalize ----
    #pragma unroll
    for (int i = 0; i < 4; i++) {
        float inv = 1.f / lrun[i];
        float* op = O + ((size_t)b * S_ + q0 + i * 32 + qx) * D_ + h * DK_ + ky * 8;
        *reinterpret_cast<float4*>(op) =
            make_float4(o[i][0].x * inv, o[i][0].y * inv,
                        o[i][0].z * inv, o[i][0].w * inv);
        *reinterpret_cast<float4*>(op + 4) =
            make_float4(o[i][1].x * inv, o[i][1].y * inv,
                        o[i][1].z * inv, o[i][1].w * inv);
    }
}

// ---------------------------------------------------------------------------
// Launch: 5 kernels, graph-capturable, no allocations / syncs.
// ---------------------------------------------------------------------------
extern "C" void kernel_launch(void* const* d_in, const int* in_sizes, int n_in,
                              void* d_out, int out_size)
{
    const float* q    = (const float*)d_in[0];
    const float* k    = (const float*)d_in[1];
    const float* v    = (const float*)d_in[2];
    const int*   mask = (const int*)  d_in[3];
    const float* w_q  = (const float*)d_in[4];
    const float* w_k  = (const float*)d_in[5];
    const float* w_v  = (const float*)d_in[6];
    const float* w_o  = (const float*)d_in[7];
    float* out = (float*)d_out;

    float *gq, *gk, *gv, *ga;
    cudaGetSymbolAddress((void**)&gq, g_Q);
    cudaGetSymbolAddress((void**)&gk, g_K);
    cudaGetSymbolAddress((void**)&gv, g_V);
    cudaGetSymbolAddress((void**)&ga, g_A);

    const int M = B_ * S_;                 // 8192
    dim3 gemm_grid(D_ / 128, M / 128);     // (8, 64)

    gemm_atb_kernel<<<gemm_grid, 256>>>(q, w_q, gq, M, D_, D_);
    gemm_atb_kernel<<<gemm_grid, 256>>>(k, w_k, gk, M, D_, D_);
    gemm_atb_kernel<<<gemm_grid, 256>>>(v, w_v, gv, M, D_, D_);

    const int attn_smem = SM_TOT * (int)sizeof(float);   // 110592 B
    cudaFuncSetAttribute(attn_kernel,
                         cudaFuncAttributeMaxDynamicSharedMemorySize, attn_smem);
    dim3 attn_grid(S_ / 128, B_ * H_);     // (16, 64)
    attn_kernel<<<attn_grid, 256, attn_smem>>>(gq, gk, gv, mask, ga);

    gemm_atb_kernel<<<gemm_grid, 256>>>(ga, w_o, out, M, D_, D_);
}

// round 9
// speedup vs baseline: 1.5874x; 1.0211x over previous
#include <cuda_runtime.h>
#include <cstdint>

#define B_  4
#define S_  2048
#define D_  1024
#define H_  16
#define DK_ 64

// Scratch (no cudaMalloc allowed; __device__ globals are the workaround).
__device__ float g_Q[(size_t)B_ * S_ * D_];
__device__ float g_K[(size_t)B_ * S_ * D_];
__device__ float g_V[(size_t)B_ * S_ * D_];
__device__ float g_A[(size_t)B_ * S_ * D_];

// ---------------------------------------------------------------------------
// tf32x3 tensor-core GEMM: C[M,N] = A[M,K] * B[N,K]^T
// Each fp32 x split as hi = tf32(x), lo = tf32(x - hi); accumulate
// Ah*Bh + Ah*Bl + Al*Bh in fp32 (error ~2e-6, lo*lo term negligible).
// BM=BN=128, BK=32, 256 thr = 8 warps (2m x 4n), warp tile 64x32,
// 4x4 m16n8k8 tiles per warp. smem: hi/lo interleaved float2, stride 35.
// 70 KB/CTA -> 2 CTAs/SM.
// NOTE: cvt.rna.tf32.f32 requires a .b32 (integer) destination register —
// "=r" constraint, not "=f" (R8 ptxas failure).
// ---------------------------------------------------------------------------
#define GBK 32
#define GST 35   // float2 stride per row

__device__ __forceinline__ float2 split_tf32(float x)
{
    uint32_t hb, lb;
    asm("cvt.rna.tf32.f32 %0, %1;" : "=r"(hb) : "f"(x));
    float hi = __uint_as_float(hb);
    float lo = x - hi;
    asm("cvt.rna.tf32.f32 %0, %1;" : "=r"(lb) : "f"(lo));
    return make_float2(hi, __uint_as_float(lb));
}

__device__ __forceinline__ void mma_tf32(float4& c,
    float a0, float a1, float a2, float a3, float b0, float b1)
{
    uint32_t ua0 = __float_as_uint(a0), ua1 = __float_as_uint(a1);
    uint32_t ua2 = __float_as_uint(a2), ua3 = __float_as_uint(a3);
    uint32_t ub0 = __float_as_uint(b0), ub1 = __float_as_uint(b1);
    asm volatile(
        "mma.sync.aligned.m16n8k8.row.col.f32.tf32.tf32.f32 "
        "{%0,%1,%2,%3}, {%4,%5,%6,%7}, {%8,%9}, {%0,%1,%2,%3};"
        : "+f"(c.x), "+f"(c.y), "+f"(c.z), "+f"(c.w)
        : "r"(ua0), "r"(ua1), "r"(ua2), "r"(ua3), "r"(ub0), "r"(ub1));
}

__global__ void __launch_bounds__(256)
gemm_tf32_kernel(const float* __restrict__ A, const float* __restrict__ Bm,
                 float* __restrict__ C, int M, int N, int Kd)
{
    extern __shared__ float2 sm2[];
    float2* As2 = sm2;                 // [128][GST]
    float2* Bs2 = sm2 + 128 * GST;     // [128][GST]

    const int tid  = threadIdx.x;
    const int lane = tid & 31;
    const int warp = tid >> 5;
    const int g    = lane >> 2;        // 0..7
    const int tig  = lane & 3;         // 0..3
    const int wm   = (warp >> 2) * 64; // 0,64
    const int wn   = (warp & 3) * 32;  // 0,32,64,96
    const int m0   = blockIdx.y * 128;
    const int n0   = blockIdx.x * 128;

    float4 acc[4][4];
    #pragma unroll
    for (int i = 0; i < 4; i++)
        #pragma unroll
        for (int j = 0; j < 4; j++) acc[i][j] = make_float4(0.f, 0.f, 0.f, 0.f);

    for (int k0 = 0; k0 < D_; k0 += GBK) {
        __syncthreads();               // previous iter's frag reads done
        // ---- stage + split: 128x32 A and B tiles, 4 float4 each/thread ----
        #pragma unroll
        for (int i = 0; i < 4; i++) {
            int idx = tid + i * 256;   // 0..1023
            int r = idx >> 3, c4 = (idx & 7) * 4;
            float4 va = *reinterpret_cast<const float4*>(
                A + (size_t)(m0 + r) * D_ + k0 + c4);
            As2[r * GST + c4 + 0] = split_tf32(va.x);
            As2[r * GST + c4 + 1] = split_tf32(va.y);
            As2[r * GST + c4 + 2] = split_tf32(va.z);
            As2[r * GST + c4 + 3] = split_tf32(va.w);
            float4 vb = *reinterpret_cast<const float4*>(
                Bm + (size_t)(n0 + r) * D_ + k0 + c4);
            Bs2[r * GST + c4 + 0] = split_tf32(vb.x);
            Bs2[r * GST + c4 + 1] = split_tf32(vb.y);
            Bs2[r * GST + c4 + 2] = split_tf32(vb.z);
            Bs2[r * GST + c4 + 3] = split_tf32(vb.w);
        }
        __syncthreads();

        #pragma unroll
        for (int ks = 0; ks < GBK / 8; ks++) {
            const int kk = ks * 8;
            float2 bf[4][2];
            #pragma unroll
            for (int tn = 0; tn < 4; tn++) {
                int n = wn + tn * 8 + g;
                bf[tn][0] = Bs2[n * GST + kk + tig];
                bf[tn][1] = Bs2[n * GST + kk + tig + 4];
            }
            #pragma unroll
            for (int tm = 0; tm < 4; tm++) {
                int r0 = wm + tm * 16 + g;
                float2 a0 = As2[r0 * GST + kk + tig];
                float2 a1 = As2[(r0 + 8) * GST + kk + tig];
                float2 a2 = As2[r0 * GST + kk + tig + 4];
                float2 a3 = As2[(r0 + 8) * GST + kk + tig + 4];
                #pragma unroll
                for (int tn = 0; tn < 4; tn++) {
                    // hi*hi, hi*lo, lo*hi (lo*lo negligible)
                    mma_tf32(acc[tm][tn], a0.x, a1.x, a2.x, a3.x,
                             bf[tn][0].x, bf[tn][1].x);
                    mma_tf32(acc[tm][tn], a0.x, a1.x, a2.x, a3.x,
                             bf[tn][0].y, bf[tn][1].y);
                    mma_tf32(acc[tm][tn], a0.y, a1.y, a2.y, a3.y,
                             bf[tn][0].x, bf[tn][1].x);
                }
            }
        }
    }

    // ---- epilogue: c0,c1 -> (row g, cols 2t,2t+1); c2,c3 -> row g+8 ----
    #pragma unroll
    for (int tm = 0; tm < 4; tm++) {
        #pragma unroll
        for (int tn = 0; tn < 4; tn++) {
            int row = m0 + wm + tm * 16 + g;
            int col = n0 + wn + tn * 8 + 2 * tig;
            *reinterpret_cast<float2*>(C + (size_t)row * N + col) =
                make_float2(acc[tm][tn].x, acc[tm][tn].y);
            *reinterpret_cast<float2*>(C + (size_t)(row + 8) * N + col) =
                make_float2(acc[tm][tn].z, acc[tm][tn].w);
        }
    }
}

// Fast exp on the FMA pipe (no MUFU): 2^x range reduction + deg-5 poly.
__device__ __forceinline__ float fexp(float x)
{
    float t = fmaxf(x * 1.4426950408889634f, -126.0f);
    float z = t + 12582912.0f;               // 1.5 * 2^23
    int  ei = __float_as_int(z) - 0x4B400000;
    float f = t - (z - 12582912.0f);         // f in [-0.5, 0.5]
    float p = fmaf(0.0013333558f, f, 0.0096181291f);
    p = fmaf(p, f, 0.0555041087f);
    p = fmaf(p, f, 0.2402265069f);
    p = fmaf(p, f, 0.6931471806f);
    p = fmaf(p, f, 1.0f);
    return __int_as_float(__float_as_int(p) + (ei << 23));
}

__device__ __forceinline__ void fma4(float4& a, float s, const float4& v)
{
    a.x = fmaf(s, v.x, a.x); a.y = fmaf(s, v.y, a.y);
    a.z = fmaf(s, v.z, a.z); a.w = fmaf(s, v.w, a.w);
}

// ---------------------------------------------------------------------------
// Register-tiled flash attention (R7 measured-good: 2.19 ms, regs 128).
// ---------------------------------------------------------------------------
#define QS_ST 68
#define KS_ST 76
#define PS_ST 72
#define SM_KS (128 * QS_ST)                    // 8704
#define SM_VS (SM_KS + 64 * KS_ST)             // 13568
#define SM_PS (SM_VS + 64 * KS_ST)             // 18432
#define SM_TOT (SM_PS + 128 * PS_ST)           // 27648 floats = 110592 B

__global__ void __launch_bounds__(256, 2)
attn_kernel(const float* __restrict__ Q, const float* __restrict__ Kt,
            const float* __restrict__ Vt, const int* __restrict__ mask,
            float* __restrict__ O)
{
    extern __shared__ float sm[];
    float* Qs = sm;
    float* Ks = sm + SM_KS;
    float* Vs = sm + SM_VS;
    float* Ps = sm + SM_PS;

    const int tid = threadIdx.x;
    const int qx  = tid >> 3;              // 0..31
    const int ky  = tid & 7;               // 0..7
    const int b   = blockIdx.y >> 4;
    const int h   = blockIdx.y & 15;
    const int q0  = blockIdx.x * 128;

    #pragma unroll
    for (int i = 0; i < 8; i++) {
        int idx = tid + i * 256;           // 0..2047
        int r = idx >> 4, c = idx & 15;
        *reinterpret_cast<float4*>(&Qs[r * QS_ST + c * 4]) =
            *reinterpret_cast<const float4*>(
                Q + ((size_t)b * S_ + q0 + r) * D_ + h * DK_ + c * 4);
    }

    float4 o[4][2];
    float mrun[4], lrun[4];
    #pragma unroll
    for (int i = 0; i < 4; i++) {
        o[i][0] = make_float4(0.f, 0.f, 0.f, 0.f);
        o[i][1] = make_float4(0.f, 0.f, 0.f, 0.f);
        mrun[i] = -1e30f; lrun[i] = 0.f;
    }

    for (int kt = 0; kt < S_; kt += 64) {
        __syncthreads();
        #pragma unroll
        for (int i = 0; i < 4; i++) {
            int idx = tid + i * 256;       // 0..1023
            int r = idx >> 4, c = idx & 15;
            size_t g = ((size_t)b * S_ + kt + r) * D_ + h * DK_ + c * 4;
            *reinterpret_cast<float4*>(&Ks[r * KS_ST + c * 4]) =
                *reinterpret_cast<const float4*>(Kt + g);
            *reinterpret_cast<float4*>(&Vs[r * KS_ST + c * 4]) =
                *reinterpret_cast<const float4*>(Vt + g);
        }
        __syncthreads();

        float s[4][8];
        #pragma unroll
        for (int i = 0; i < 4; i++)
            #pragma unroll
            for (int j = 0; j < 8; j++) s[i][j] = 0.f;

        #pragma unroll
        for (int d4 = 0; d4 < 16; d4++) {
            float4 kv[8];
            #pragma unroll
            for (int j = 0; j < 8; j++)
                kv[j] = *reinterpret_cast<const float4*>(
                    &Ks[(j * 8 + ky) * KS_ST + d4 * 4]);
            #pragma unroll
            for (int i = 0; i < 4; i++) {
                float4 qv = *reinterpret_cast<const float4*>(
                    &Qs[(i * 32 + qx) * QS_ST + d4 * 4]);
                #pragma unroll
                for (int j = 0; j < 8; j++) {
                    float acc = s[i][j];
                    acc = fmaf(qv.x, kv[j].x, acc);
                    acc = fmaf(qv.y, kv[j].y, acc);
                    acc = fmaf(qv.z, kv[j].z, acc);
                    acc = fmaf(qv.w, kv[j].w, acc);
                    s[i][j] = acc;
                }
            }
        }

        #pragma unroll
        for (int i = 0; i < 4; i++) {
            const int qrow = q0 + i * 32 + qx;
            const int* mp = mask + ((size_t)b * S_ + qrow) * S_ + kt;
            float rm = -1e30f;
            #pragma unroll
            for (int j = 0; j < 8; j++) {
                float sv = s[i][j] * 0.125f;            // 1/sqrt(64)
                if (mp[j * 8 + ky] == 0) sv = -1e9f;
                s[i][j] = sv;
                rm = fmaxf(rm, sv);
            }
            rm = fmaxf(rm, __shfl_xor_sync(0xffffffffu, rm, 1));
            rm = fmaxf(rm, __shfl_xor_sync(0xffffffffu, rm, 2));
            rm = fmaxf(rm, __shfl_xor_sync(0xffffffffu, rm, 4));

            float mnew = fmaxf(mrun[i], rm);
            float corr = fexp(mrun[i] - mnew);
            float lr   = lrun[i] * corr;
            o[i][0].x *= corr; o[i][0].y *= corr;
            o[i][0].z *= corr; o[i][0].w *= corr;
            o[i][1].x *= corr; o[i][1].y *= corr;
            o[i][1].z *= corr; o[i][1].w *= corr;

            float sum = 0.f;
            #pragma unroll
            for (int j = 0; j < 8; j++) {
                float p = fexp(s[i][j] - mnew);
                sum += p;
                Ps[(i * 32 + qx) * PS_ST + j * 8 + ky] = p;
            }
            sum += __shfl_xor_sync(0xffffffffu, sum, 1);
            sum += __shfl_xor_sync(0xffffffffu, sum, 2);
            sum += __shfl_xor_sync(0xffffffffu, sum, 4);

            lrun[i] = lr + sum;
            mrun[i] = mnew;
        }
        __syncthreads();

        #pragma unroll
        for (int k4 = 0; k4 < 64; k4 += 4) {
            float4 pa[4];
            #pragma unroll
            for (int i = 0; i < 4; i++)
                pa[i] = *reinterpret_cast<const float4*>(
                    &Ps[(i * 32 + qx) * PS_ST + k4]);
            float4 va[4], vb[4];
            #pragma unroll
            for (int t = 0; t < 4; t++) {
                va[t] = *reinterpret_cast<const float4*>(
                    &Vs[(k4 + t) * KS_ST + ky * 8]);
                vb[t] = *reinterpret_cast<const float4*>(
                    &Vs[(k4 + t) * KS_ST + ky * 8 + 4]);
            }
            #pragma unroll
            for (int i = 0; i < 4; i++) {
                fma4(o[i][0], pa[i].x, va[0]); fma4(o[i][1], pa[i].x, vb[0]);
                fma4(o[i][0], pa[i].y, va[1]); fma4(o[i][1], pa[i].y, vb[1]);
                fma4(o[i][0], pa[i].z, va[2]); fma4(o[i][1], pa[i].z, vb[2]);
                fma4(o[i][0], pa[i].w, va[3]); fma4(o[i][1], pa[i].w, vb[3]);
            }
        }
    }

    #pragma unroll
    for (int i = 0; i < 4; i++) {
        float inv = 1.f / lrun[i];
        float* op = O + ((size_t)b * S_ + q0 + i * 32 + qx) * D_ + h * DK_ + ky * 8;
        *reinterpret_cast<float4*>(op) =
            make_float4(o[i][0].x * inv, o[i][0].y * inv,
                        o[i][0].z * inv, o[i][0].w * inv);
        *reinterpret_cast<float4*>(op + 4) =
            make_float4(o[i][1].x * inv, o[i][1].y * inv,
                        o[i][1].z * inv, o[i][1].w * inv);
    }
}

// ---------------------------------------------------------------------------
// Launch: 5 kernels, graph-capturable, no allocations / syncs.
// ---------------------------------------------------------------------------
extern "C" void kernel_launch(void* const* d_in, const int* in_sizes, int n_in,
                              void* d_out, int out_size)
{
    const float* q    = (const float*)d_in[0];
    const float* k    = (const float*)d_in[1];
    const float* v    = (const float*)d_in[2];
    const int*   mask = (const int*)  d_in[3];
    const float* w_q  = (const float*)d_in[4];
    const float* w_k  = (const float*)d_in[5];
    const float* w_v  = (const float*)d_in[6];
    const float* w_o  = (const float*)d_in[7];
    float* out = (float*)d_out;

    float *gq, *gk, *gv, *ga;
    cudaGetSymbolAddress((void**)&gq, g_Q);
    cudaGetSymbolAddress((void**)&gk, g_K);
    cudaGetSymbolAddress((void**)&gv, g_V);
    cudaGetSymbolAddress((void**)&ga, g_A);

    const int M = B_ * S_;                 // 8192
    dim3 gemm_grid(D_ / 128, M / 128);     // (8, 64)

    const int gemm_smem = 2 * 128 * GST * (int)sizeof(float2);   // 71680 B
    cudaFuncSetAttribute(gemm_tf32_kernel,
                         cudaFuncAttributeMaxDynamicSharedMemorySize, gemm_smem);

    gemm_tf32_kernel<<<gemm_grid, 256, gemm_smem>>>(q, w_q, gq, M, D_, D_);
    gemm_tf32_kernel<<<gemm_grid, 256, gemm_smem>>>(k, w_k, gk, M, D_, D_);
    gemm_tf32_kernel<<<gemm_grid, 256, gemm_smem>>>(v, w_v, gv, M, D_, D_);

    const int attn_smem = SM_TOT * (int)sizeof(float);   // 110592 B
    cudaFuncSetAttribute(attn_kernel,
                         cudaFuncAttributeMaxDynamicSharedMemorySize, attn_smem);
    dim3 attn_grid(S_ / 128, B_ * H_);     // (16, 64)
    attn_kernel<<<attn_grid, 256, attn_smem>>>(gq, gk, gv, mask, ga);

    gemm_tf32_kernel<<<gemm_grid, 256, gemm_smem>>>(ga, w_o, out, M, D_, D_);
}

// round 11
// speedup vs baseline: 2.0659x; 1.3014x over previous
#include <cuda_runtime.h>
#include <cuda_bf16.h>
#include <cstdint>

#define B_  4
#define S_  2048
#define D_  1024
#define H_  16
#define DK_ 64

// Scratch (no cudaMalloc allowed; __device__ globals are the workaround).
__device__ float g_Q[(size_t)B_ * S_ * D_];
__device__ float g_K[(size_t)B_ * S_ * D_];
__device__ float g_V[(size_t)B_ * S_ * D_];
__device__ float g_A[(size_t)B_ * S_ * D_];

// ===========================================================================
// bf16x3 tensor-core GEMM via mma.sync.m16n8k16 (sm_100 baseline ISA;
// tcgen05 is sm_100a-only and this harness compiles to target sm_100).
// C[M,N] = A[M,K] * B[N,K]^T.  x = bf16_hi + bf16_lo;
// C += Ah*Bh + Ah*Bl + Al*Bh  (ll + rounding ~ 3*2^-18/term -> rel err ~5e-5).
// BM=BN=128, BK=64, 256 thr = 8 warps (2m x 4n), warp tile 64x32,
// 4x4 m16n8k16 tiles per warp. smem: 4 bf16-pair buffers (Ah,Al,Bh,Bl),
// u32 stride 36 -> fragment loads bank = (4g + tig + c) mod 32, conflict-free.
// 73728 B/CTA -> 2 CTAs/SM.
// ===========================================================================
#define GBK 64
#define AST 36                      // u32 (bf16-pair) stride per row
#define BUF (128 * AST)             // 4608 u32 per buffer

__device__ __forceinline__ uint32_t pack_bf16(__nv_bfloat16 a, __nv_bfloat16 b)
{
    return (uint32_t)__bfloat16_as_ushort(a) |
           ((uint32_t)__bfloat16_as_ushort(b) << 16);
}

// Split float4 (4 consecutive k) into hi/lo bf16-pair uint2 and store.
__device__ __forceinline__ void split_store(uint32_t* hi, uint32_t* lo,
                                            int base, float4 v)
{
    __nv_bfloat16 hx = __float2bfloat16(v.x), hy = __float2bfloat16(v.y);
    __nv_bfloat16 hz = __float2bfloat16(v.z), hw = __float2bfloat16(v.w);
    *reinterpret_cast<uint2*>(hi + base) =
        make_uint2(pack_bf16(hx, hy), pack_bf16(hz, hw));
    __nv_bfloat16 lx = __float2bfloat16(v.x - __bfloat162float(hx));
    __nv_bfloat16 ly = __float2bfloat16(v.y - __bfloat162float(hy));
    __nv_bfloat16 lz = __float2bfloat16(v.z - __bfloat162float(hz));
    __nv_bfloat16 lw = __float2bfloat16(v.w - __bfloat162float(hw));
    *reinterpret_cast<uint2*>(lo + base) =
        make_uint2(pack_bf16(lx, ly), pack_bf16(lz, lw));
}

__device__ __forceinline__ void mma_bf16(float4& c,
    uint32_t a0, uint32_t a1, uint32_t a2, uint32_t a3,
    uint32_t b0, uint32_t b1)
{
    asm volatile(
        "mma.sync.aligned.m16n8k16.row.col.f32.bf16.bf16.f32 "
        "{%0,%1,%2,%3}, {%4,%5,%6,%7}, {%8,%9}, {%0,%1,%2,%3};"
        : "+f"(c.x), "+f"(c.y), "+f"(c.z), "+f"(c.w)
        : "r"(a0), "r"(a1), "r"(a2), "r"(a3), "r"(b0), "r"(b1));
}

__global__ void __launch_bounds__(256, 2)
gemm_bf16_kernel(const float* __restrict__ A, const float* __restrict__ Bm,
                 float* __restrict__ C, int M, int N, int Kd)
{
    extern __shared__ uint32_t smu[];
    uint32_t* Ah = smu;
    uint32_t* Al = smu + BUF;
    uint32_t* Bh = smu + 2 * BUF;
    uint32_t* Bl = smu + 3 * BUF;

    const int tid  = threadIdx.x;
    const int lane = tid & 31;
    const int warp = tid >> 5;
    const int g    = lane >> 2;        // 0..7
    const int tig  = lane & 3;         // 0..3
    const int wm   = (warp >> 2) * 64; // 0,64
    const int wn   = (warp & 3) * 32;  // 0,32,64,96
    const int m0   = blockIdx.y * 128;
    const int n0   = blockIdx.x * 128;

    float4 acc[4][4];
    #pragma unroll
    for (int i = 0; i < 4; i++)
        #pragma unroll
        for (int j = 0; j < 4; j++) acc[i][j] = make_float4(0.f, 0.f, 0.f, 0.f);

    for (int k0 = 0; k0 < D_; k0 += GBK) {
        __syncthreads();               // previous iter's fragment reads done
        // ---- stage + split: 128x64 A and B tiles; 8 float4 each/thread ----
        #pragma unroll
        for (int i = 0; i < 8; i++) {
            int idx = tid + i * 256;   // 0..2047
            int r = idx >> 4, c4 = (idx & 15) * 4;
            int base = r * AST + (c4 >> 1);
            float4 va = *reinterpret_cast<const float4*>(
                A + (size_t)(m0 + r) * D_ + k0 + c4);
            split_store(Ah, Al, base, va);
            float4 vb = *reinterpret_cast<const float4*>(
                Bm + (size_t)(n0 + r) * D_ + k0 + c4);
            split_store(Bh, Bl, base, vb);
        }
        __syncthreads();

        #pragma unroll
        for (int ks = 0; ks < GBK / 16; ks++) {
            const int cb = ks * 8 + tig;     // bf16-pair column
            uint32_t bh[4][2], bl[4][2];
            #pragma unroll
            for (int tn = 0; tn < 4; tn++) {
                int n = (wn + tn * 8 + g) * AST;
                bh[tn][0] = Bh[n + cb]; bh[tn][1] = Bh[n + cb + 4];
                bl[tn][0] = Bl[n + cb]; bl[tn][1] = Bl[n + cb + 4];
            }
            #pragma unroll
            for (int tm = 0; tm < 4; tm++) {
                int r0 = (wm + tm * 16 + g) * AST;
                int r1 = r0 + 8 * AST;
                uint32_t ah0 = Ah[r0 + cb],     ah1 = Ah[r1 + cb];
                uint32_t ah2 = Ah[r0 + cb + 4], ah3 = Ah[r1 + cb + 4];
                uint32_t al0 = Al[r0 + cb],     al1 = Al[r1 + cb];
                uint32_t al2 = Al[r0 + cb + 4], al3 = Al[r1 + cb + 4];
                #pragma unroll
                for (int tn = 0; tn < 4; tn++) {
                    mma_bf16(acc[tm][tn], ah0, ah1, ah2, ah3,
                             bh[tn][0], bh[tn][1]);
                    mma_bf16(acc[tm][tn], ah0, ah1, ah2, ah3,
                             bl[tn][0], bl[tn][1]);
                    mma_bf16(acc[tm][tn], al0, al1, al2, al3,
                             bh[tn][0], bh[tn][1]);
                }
            }
        }
    }

    // ---- epilogue: c0,c1 -> (row g, cols 2t,2t+1); c2,c3 -> row g+8 ----
    #pragma unroll
    for (int tm = 0; tm < 4; tm++) {
        #pragma unroll
        for (int tn = 0; tn < 4; tn++) {
            int row = m0 + wm + tm * 16 + g;
            int col = n0 + wn + tn * 8 + 2 * tig;
            *reinterpret_cast<float2*>(C + (size_t)row * N + col) =
                make_float2(acc[tm][tn].x, acc[tm][tn].y);
            *reinterpret_cast<float2*>(C + (size_t)(row + 8) * N + col) =
                make_float2(acc[tm][tn].z, acc[tm][tn].w);
        }
    }
}

// ===========================================================================
// Fast exp on the FMA pipe (no MUFU): 2^x range reduction + deg-5 poly.
// ===========================================================================
__device__ __forceinline__ float fexp(float x)
{
    float t = fmaxf(x * 1.4426950408889634f, -126.0f);
    float z = t + 12582912.0f;               // 1.5 * 2^23
    int  ei = __float_as_int(z) - 0x4B400000;
    float f = t - (z - 12582912.0f);         // f in [-0.5, 0.5]
    float p = fmaf(0.0013333558f, f, 0.0096181291f);
    p = fmaf(p, f, 0.0555041087f);
    p = fmaf(p, f, 0.2402265069f);
    p = fmaf(p, f, 0.6931471806f);
    p = fmaf(p, f, 1.0f);
    return __int_as_float(__float_as_int(p) + (ei << 23));
}

__device__ __forceinline__ void fma4(float4& a, float s, const float4& v)
{
    a.x = fmaf(s, v.x, a.x); a.y = fmaf(s, v.y, a.y);
    a.z = fmaf(s, v.z, a.z); a.w = fmaf(s, v.w, a.w);
}

// ---------------------------------------------------------------------------
// Register-tiled flash attention (measured-good: 2.17 ms, regs 128). Unchanged.
// ---------------------------------------------------------------------------
#define QS_ST 68
#define KS_ST 76
#define PS_ST 72
#define SM_KS (128 * QS_ST)                    // 8704
#define SM_VS (SM_KS + 64 * KS_ST)             // 13568
#define SM_PS (SM_VS + 64 * KS_ST)             // 18432
#define SM_TOT (SM_PS + 128 * PS_ST)           // 27648 floats = 110592 B

__global__ void __launch_bounds__(256, 2)
attn_kernel(const float* __restrict__ Q, const float* __restrict__ Kt,
            const float* __restrict__ Vt, const int* __restrict__ mask,
            float* __restrict__ O)
{
    extern __shared__ float sm[];
    float* Qs = sm;
    float* Ks = sm + SM_KS;
    float* Vs = sm + SM_VS;
    float* Ps = sm + SM_PS;

    const int tid = threadIdx.x;
    const int qx  = tid >> 3;              // 0..31
    const int ky  = tid & 7;               // 0..7
    const int b   = blockIdx.y >> 4;
    const int h   = blockIdx.y & 15;
    const int q0  = blockIdx.x * 128;

    #pragma unroll
    for (int i = 0; i < 8; i++) {
        int idx = tid + i * 256;           // 0..2047
        int r = idx >> 4, c = idx & 15;
        *reinterpret_cast<float4*>(&Qs[r * QS_ST + c * 4]) =
            *reinterpret_cast<const float4*>(
                Q + ((size_t)b * S_ + q0 + r) * D_ + h * DK_ + c * 4);
    }

    float4 o[4][2];
    float mrun[4], lrun[4];
    #pragma unroll
    for (int i = 0; i < 4; i++) {
        o[i][0] = make_float4(0.f, 0.f, 0.f, 0.f);
        o[i][1] = make_float4(0.f, 0.f, 0.f, 0.f);
        mrun[i] = -1e30f; lrun[i] = 0.f;
    }

    for (int kt = 0; kt < S_; kt += 64) {
        __syncthreads();
        #pragma unroll
        for (int i = 0; i < 4; i++) {
            int idx = tid + i * 256;       // 0..1023
            int r = idx >> 4, c = idx & 15;
            size_t g = ((size_t)b * S_ + kt + r) * D_ + h * DK_ + c * 4;
            *reinterpret_cast<float4*>(&Ks[r * KS_ST + c * 4]) =
                *reinterpret_cast<const float4*>(Kt + g);
            *reinterpret_cast<float4*>(&Vs[r * KS_ST + c * 4]) =
                *reinterpret_cast<const float4*>(Vt + g);
        }
        __syncthreads();

        float s[4][8];
        #pragma unroll
        for (int i = 0; i < 4; i++)
            #pragma unroll
            for (int j = 0; j < 8; j++) s[i][j] = 0.f;

        #pragma unroll
        for (int d4 = 0; d4 < 16; d4++) {
            float4 kv[8];
            #pragma unroll
            for (int j = 0; j < 8; j++)
                kv[j] = *reinterpret_cast<const float4*>(
                    &Ks[(j * 8 + ky) * KS_ST + d4 * 4]);
            #pragma unroll
            for (int i = 0; i < 4; i++) {
                float4 qv = *reinterpret_cast<const float4*>(
                    &Qs[(i * 32 + qx) * QS_ST + d4 * 4]);
                #pragma unroll
                for (int j = 0; j < 8; j++) {
                    float acc = s[i][j];
                    acc = fmaf(qv.x, kv[j].x, acc);
                    acc = fmaf(qv.y, kv[j].y, acc);
                    acc = fmaf(qv.z, kv[j].z, acc);
                    acc = fmaf(qv.w, kv[j].w, acc);
                    s[i][j] = acc;
                }
            }
        }

        #pragma unroll
        for (int i = 0; i < 4; i++) {
            const int qrow = q0 + i * 32 + qx;
            const int* mp = mask + ((size_t)b * S_ + qrow) * S_ + kt;
            float rm = -1e30f;
            #pragma unroll
            for (int j = 0; j < 8; j++) {
                float sv = s[i][j] * 0.125f;            // 1/sqrt(64)
                if (mp[j * 8 + ky] == 0) sv = -1e9f;
                s[i][j] = sv;
                rm = fmaxf(rm, sv);
            }
            rm = fmaxf(rm, __shfl_xor_sync(0xffffffffu, rm, 1));
            rm = fmaxf(rm, __shfl_xor_sync(0xffffffffu, rm, 2));
            rm = fmaxf(rm, __shfl_xor_sync(0xffffffffu, rm, 4));

            float mnew = fmaxf(mrun[i], rm);
            float corr = fexp(mrun[i] - mnew);
            float lr   = lrun[i] * corr;
            o[i][0].x *= corr; o[i][0].y *= corr;
            o[i][0].z *= corr; o[i][0].w *= corr;
            o[i][1].x *= corr; o[i][1].y *= corr;
            o[i][1].z *= corr; o[i][1].w *= corr;

            float sum = 0.f;
            #pragma unroll
            for (int j = 0; j < 8; j++) {
                float p = fexp(s[i][j] - mnew);
                sum += p;
                Ps[(i * 32 + qx) * PS_ST + j * 8 + ky] = p;
            }
            sum += __shfl_xor_sync(0xffffffffu, sum, 1);
            sum += __shfl_xor_sync(0xffffffffu, sum, 2);
            sum += __shfl_xor_sync(0xffffffffu, sum, 4);

            lrun[i] = lr + sum;
            mrun[i] = mnew;
        }
        __syncthreads();

        #pragma unroll
        for (int k4 = 0; k4 < 64; k4 += 4) {
            float4 pa[4];
            #pragma unroll
            for (int i = 0; i < 4; i++)
                pa[i] = *reinterpret_cast<const float4*>(
                    &Ps[(i * 32 + qx) * PS_ST + k4]);
            float4 va[4], vb[4];
            #pragma unroll
            for (int t = 0; t < 4; t++) {
                va[t] = *reinterpret_cast<const float4*>(
                    &Vs[(k4 + t) * KS_ST + ky * 8]);
                vb[t] = *reinterpret_cast<const float4*>(
                    &Vs[(k4 + t) * KS_ST + ky * 8 + 4]);
            }
            #pragma unroll
            for (int i = 0; i < 4; i++) {
                fma4(o[i][0], pa[i].x, va[0]); fma4(o[i][1], pa[i].x, vb[0]);
                fma4(o[i][0], pa[i].y, va[1]); fma4(o[i][1], pa[i].y, vb[1]);
                fma4(o[i][0], pa[i].z, va[2]); fma4(o[i][1], pa[i].z, vb[2]);
                fma4(o[i][0], pa[i].w, va[3]); fma4(o[i][1], pa[i].w, vb[3]);
            }
        }
    }

    #pragma unroll
    for (int i = 0; i < 4; i++) {
        float inv = 1.f / lrun[i];
        float* op = O + ((size_t)b * S_ + q0 + i * 32 + qx) * D_ + h * DK_ + ky * 8;
        *reinterpret_cast<float4*>(op) =
            make_float4(o[i][0].x * inv, o[i][0].y * inv,
                        o[i][0].z * inv, o[i][0].w * inv);
        *reinterpret_cast<float4*>(op + 4) =
            make_float4(o[i][1].x * inv, o[i][1].y * inv,
                        o[i][1].z * inv, o[i][1].w * inv);
    }
}

// ---------------------------------------------------------------------------
// Launch: 5 kernels, graph-capturable, no allocations / syncs.
// ---------------------------------------------------------------------------
extern "C" void kernel_launch(void* const* d_in, const int* in_sizes, int n_in,
                              void* d_out, int out_size)
{
    const float* q    = (const float*)d_in[0];
    const float* k    = (const float*)d_in[1];
    const float* v    = (const float*)d_in[2];
    const int*   mask = (const int*)  d_in[3];
    const float* w_q  = (const float*)d_in[4];
    const float* w_k  = (const float*)d_in[5];
    const float* w_v  = (const float*)d_in[6];
    const float* w_o  = (const float*)d_in[7];
    float* out = (float*)d_out;

    float *gq, *gk, *gv, *ga;
    cudaGetSymbolAddress((void**)&gq, g_Q);
    cudaGetSymbolAddress((void**)&gk, g_K);
    cudaGetSymbolAddress((void**)&gv, g_V);
    cudaGetSymbolAddress((void**)&ga, g_A);

    const int M = B_ * S_;                 // 8192
    dim3 gemm_grid(D_ / 128, M / 128);     // (8, 64)

    const int gemm_smem = 4 * BUF * (int)sizeof(uint32_t);   // 73728 B
    cudaFuncSetAttribute(gemm_bf16_kernel,
                         cudaFuncAttributeMaxDynamicSharedMemorySize, gemm_smem);

    gemm_bf16_kernel<<<gemm_grid, 256, gemm_smem>>>(q, w_q, gq, M, D_, D_);
    gemm_bf16_kernel<<<gemm_grid, 256, gemm_smem>>>(k, w_k, gk, M, D_, D_);
    gemm_bf16_kernel<<<gemm_grid, 256, gemm_smem>>>(v, w_v, gv, M, D_, D_);

    const int attn_smem = SM_TOT * (int)sizeof(float);   // 110592 B
    cudaFuncSetAttribute(attn_kernel,
                         cudaFuncAttributeMaxDynamicSharedMemorySize, attn_smem);
    dim3 attn_grid(S_ / 128, B_ * H_);     // (16, 64)
    attn_kernel<<<attn_grid, 256, attn_smem>>>(gq, gk, gv, mask, ga);

    gemm_bf16_kernel<<<gemm_grid, 256, gemm_smem>>>(ga, w_o, out, M, D_, D_);
}

// round 12
// speedup vs baseline: 3.6274x; 1.7559x over previous
#include <cuda_runtime.h>
#include <cuda_bf16.h>
#include <cstdint>

#define B_  4
#define S_  2048
#define D_  1024
#define H_  16
#define DK_ 64

// Scratch (no cudaMalloc allowed; __device__ globals are the workaround).
__device__ float g_Q[(size_t)B_ * S_ * D_];
__device__ float g_K[(size_t)B_ * S_ * D_];
__device__ float g_V[(size_t)B_ * S_ * D_];
__device__ float g_A[(size_t)B_ * S_ * D_];

// ===========================================================================
// Common bf16 helpers
// ===========================================================================
__device__ __forceinline__ uint32_t pack_bf16(__nv_bfloat16 a, __nv_bfloat16 b)
{
    return (uint32_t)__bfloat16_as_ushort(a) |
           ((uint32_t)__bfloat16_as_ushort(b) << 16);
}

__device__ __forceinline__ void split_store(uint32_t* hi, uint32_t* lo,
                                            int base, float4 v)
{
    __nv_bfloat16 hx = __float2bfloat16(v.x), hy = __float2bfloat16(v.y);
    __nv_bfloat16 hz = __float2bfloat16(v.z), hw = __float2bfloat16(v.w);
    *reinterpret_cast<uint2*>(hi + base) =
        make_uint2(pack_bf16(hx, hy), pack_bf16(hz, hw));
    __nv_bfloat16 lx = __float2bfloat16(v.x - __bfloat162float(hx));
    __nv_bfloat16 ly = __float2bfloat16(v.y - __bfloat162float(hy));
    __nv_bfloat16 lz = __float2bfloat16(v.z - __bfloat162float(hz));
    __nv_bfloat16 lw = __float2bfloat16(v.w - __bfloat162float(hw));
    *reinterpret_cast<uint2*>(lo + base) =
        make_uint2(pack_bf16(lx, ly), pack_bf16(lz, lw));
}

__device__ __forceinline__ void mma_bf16(float4& c,
    uint32_t a0, uint32_t a1, uint32_t a2, uint32_t a3,
    uint32_t b0, uint32_t b1)
{
    asm volatile(
        "mma.sync.aligned.m16n8k16.row.col.f32.bf16.bf16.f32 "
        "{%0,%1,%2,%3}, {%4,%5,%6,%7}, {%8,%9}, {%0,%1,%2,%3};"
        : "+f"(c.x), "+f"(c.y), "+f"(c.z), "+f"(c.w)
        : "r"(a0), "r"(a1), "r"(a2), "r"(a3), "r"(b0), "r"(b1));
}

// Fast exp on the FMA pipe (no MUFU): 2^x range reduction + deg-5 poly.
__device__ __forceinline__ float fexp(float x)
{
    float t = fmaxf(x * 1.4426950408889634f, -126.0f);
    float z = t + 12582912.0f;               // 1.5 * 2^23
    int  ei = __float_as_int(z) - 0x4B400000;
    float f = t - (z - 12582912.0f);         // f in [-0.5, 0.5]
    float p = fmaf(0.0013333558f, f, 0.0096181291f);
    p = fmaf(p, f, 0.0555041087f);
    p = fmaf(p, f, 0.2402265069f);
    p = fmaf(p, f, 0.6931471806f);
    p = fmaf(p, f, 1.0f);
    return __int_as_float(__float_as_int(p) + (ei << 23));
}

// ===========================================================================
// bf16x3 tensor-core GEMM (R11 measured-good: ~190 us each). Unchanged.
// ===========================================================================
#define GBK 64
#define AST 36
#define BUF (128 * AST)

__global__ void __launch_bounds__(256, 2)
gemm_bf16_kernel(const float* __restrict__ A, const float* __restrict__ Bm,
                 float* __restrict__ C, int M, int N, int Kd)
{
    extern __shared__ uint32_t smu[];
    uint32_t* Ah = smu;
    uint32_t* Al = smu + BUF;
    uint32_t* Bh = smu + 2 * BUF;
    uint32_t* Bl = smu + 3 * BUF;

    const int tid  = threadIdx.x;
    const int lane = tid & 31;
    const int warp = tid >> 5;
    const int g    = lane >> 2;
    const int tig  = lane & 3;
    const int wm   = (warp >> 2) * 64;
    const int wn   = (warp & 3) * 32;
    const int m0   = blockIdx.y * 128;
    const int n0   = blockIdx.x * 128;

    float4 acc[4][4];
    #pragma unroll
    for (int i = 0; i < 4; i++)
        #pragma unroll
        for (int j = 0; j < 4; j++) acc[i][j] = make_float4(0.f, 0.f, 0.f, 0.f);

    for (int k0 = 0; k0 < D_; k0 += GBK) {
        __syncthreads();
        #pragma unroll
        for (int i = 0; i < 8; i++) {
            int idx = tid + i * 256;
            int r = idx >> 4, c4 = (idx & 15) * 4;
            int base = r * AST + (c4 >> 1);
            float4 va = *reinterpret_cast<const float4*>(
                A + (size_t)(m0 + r) * D_ + k0 + c4);
            split_store(Ah, Al, base, va);
            float4 vb = *reinterpret_cast<const float4*>(
                Bm + (size_t)(n0 + r) * D_ + k0 + c4);
            split_store(Bh, Bl, base, vb);
        }
        __syncthreads();

        #pragma unroll
        for (int ks = 0; ks < GBK / 16; ks++) {
            const int cb = ks * 8 + tig;
            uint32_t bh[4][2], bl[4][2];
            #pragma unroll
            for (int tn = 0; tn < 4; tn++) {
                int n = (wn + tn * 8 + g) * AST;
                bh[tn][0] = Bh[n + cb]; bh[tn][1] = Bh[n + cb + 4];
                bl[tn][0] = Bl[n + cb]; bl[tn][1] = Bl[n + cb + 4];
            }
            #pragma unroll
            for (int tm = 0; tm < 4; tm++) {
                int r0 = (wm + tm * 16 + g) * AST;
                int r1 = r0 + 8 * AST;
                uint32_t ah0 = Ah[r0 + cb],     ah1 = Ah[r1 + cb];
                uint32_t ah2 = Ah[r0 + cb + 4], ah3 = Ah[r1 + cb + 4];
                uint32_t al0 = Al[r0 + cb],     al1 = Al[r1 + cb];
                uint32_t al2 = Al[r0 + cb + 4], al3 = Al[r1 + cb + 4];
                #pragma unroll
                for (int tn = 0; tn < 4; tn++) {
                    mma_bf16(acc[tm][tn], ah0, ah1, ah2, ah3,
                             bh[tn][0], bh[tn][1]);
                    mma_bf16(acc[tm][tn], ah0, ah1, ah2, ah3,
                             bl[tn][0], bl[tn][1]);
                    mma_bf16(acc[tm][tn], al0, al1, al2, al3,
                             bh[tn][0], bh[tn][1]);
                }
            }
        }
    }

    #pragma unroll
    for (int tm = 0; tm < 4; tm++) {
        #pragma unroll
        for (int tn = 0; tn < 4; tn++) {
            int row = m0 + wm + tm * 16 + g;
            int col = n0 + wn + tn * 8 + 2 * tig;
            *reinterpret_cast<float2*>(C + (size_t)row * N + col) =
                make_float2(acc[tm][tn].x, acc[tm][tn].y);
            *reinterpret_cast<float2*>(C + (size_t)(row + 8) * N + col) =
                make_float2(acc[tm][tn].z, acc[tm][tn].w);
        }
    }
}

// ===========================================================================
// bf16x3 mma flash attention.
// CTA: 256 thr = 8 warps, 128-query tile, one (b,h). Warp w owns queries
// qbase = q0 + w*16 (rows g and g+8 per lane group), all keys, all 64 d.
// Per 64-key tile:
//   QK^T : S frags sacc[8] (8 n-tiles of 8 keys), bf16 hi/lo x3 mma.
//   softmax: rows within lane group (shfl over tig); online m/l in regs.
//   P->A frags (register reuse, bf16 hi/lo); PV with V^T staged in smem.
// smem: Qh/Ql[128][36], Kh/Kl[64][36], Vth/Vtl[64][36] u32 = 73728 B
//  -> 2 CTAs/SM.
// ===========================================================================
#define AQH 0
#define AQL (128 * AST)          // 4608
#define AKH (2 * 128 * AST)      // 9216
#define AKL (AKH + 64 * AST)     // 11520
#define AVH (AKL + 64 * AST)     // 13824
#define AVL (AVH + 64 * AST)     // 16128
#define ATOT (AVL + 64 * AST)    // 18432 u32 = 73728 B

__global__ void __launch_bounds__(256, 2)
attn_mma_kernel(const float* __restrict__ Q, const float* __restrict__ Kt,
                const float* __restrict__ Vt, const int* __restrict__ mask,
                float* __restrict__ O)
{
    extern __shared__ uint32_t smu[];
    uint32_t* Qh  = smu + AQH;
    uint32_t* Ql  = smu + AQL;
    uint32_t* Kh  = smu + AKH;
    uint32_t* Kl  = smu + AKL;
    uint32_t* Vth = smu + AVH;
    uint32_t* Vtl = smu + AVL;

    const int tid  = threadIdx.x;
    const int lane = tid & 31;
    const int warp = tid >> 5;           // 0..7
    const int g    = lane >> 2;          // 0..7
    const int tig  = lane & 3;           // 0..3
    const int b    = blockIdx.y >> 4;
    const int h    = blockIdx.y & 15;
    const int q0   = blockIdx.x * 128;
    const int qb   = q0 + warp * 16;     // warp's query base

    // ---- stage Q tile [128 x 64] hi/lo (once) ----
    #pragma unroll
    for (int i = 0; i < 8; i++) {
        int idx = tid + i * 256;         // 0..2047
        int r = idx >> 4, c4 = (idx & 15) * 4;
        float4 v = *reinterpret_cast<const float4*>(
            Q + ((size_t)b * S_ + q0 + r) * D_ + h * DK_ + c4);
        split_store(Qh, Ql, r * AST + (c4 >> 1), v);
    }

    float4 oacc[8];
    #pragma unroll
    for (int i = 0; i < 8; i++) oacc[i] = make_float4(0.f, 0.f, 0.f, 0.f);
    float mrun0 = -1e30f, mrun1 = -1e30f, lrun0 = 0.f, lrun1 = 0.f;

    const int vp = tid & 31;             // key pair for V staging
    const int vd = (tid >> 5) * 8;       // d-group for V staging

    for (int kt = 0; kt < S_; kt += 64) {
        __syncthreads();                 // prior tile reads done (covers Q too)
        // ---- stage K tile [64 keys x 64 d] hi/lo ----
        #pragma unroll
        for (int i = 0; i < 4; i++) {
            int idx = tid + i * 256;     // 0..1023
            int r = idx >> 4, c4 = (idx & 15) * 4;
            float4 v = *reinterpret_cast<const float4*>(
                Kt + ((size_t)b * S_ + kt + r) * D_ + h * DK_ + c4);
            split_store(Kh, Kl, r * AST + (c4 >> 1), v);
        }
        // ---- stage V^T [64 d x 64 keys] hi/lo, key pairs packed per u32 ----
        {
            const float* v0p = Vt + ((size_t)b * S_ + kt + 2 * vp) * D_ + h * DK_ + vd;
            const float* v1p = v0p + D_;
            float4 v0a = *reinterpret_cast<const float4*>(v0p);
            float4 v0b = *reinterpret_cast<const float4*>(v0p + 4);
            float4 v1a = *reinterpret_cast<const float4*>(v1p);
            float4 v1b = *reinterpret_cast<const float4*>(v1p + 4);
            const float* e0 = &v0a.x;   // 8 d values for key 2vp
            const float* e1 = &v1a.x;   // 8 d values for key 2vp+1
            #pragma unroll
            for (int j = 0; j < 8; j++) {
                float x0 = (j < 4) ? e0[j] : (&v0b.x)[j - 4];
                float x1 = (j < 4) ? e1[j] : (&v1b.x)[j - 4];
                __nv_bfloat16 h0 = __float2bfloat16(x0);
                __nv_bfloat16 h1 = __float2bfloat16(x1);
                Vth[(vd + j) * AST + vp] = pack_bf16(h0, h1);
                Vtl[(vd + j) * AST + vp] = pack_bf16(
                    __float2bfloat16(x0 - __bfloat162float(h0)),
                    __float2bfloat16(x1 - __bfloat162float(h1)));
            }
        }
        __syncthreads();

        // ---- phase 1: S = Q K^T (bf16x3) ----
        float4 sacc[8];
        #pragma unroll
        for (int j = 0; j < 8; j++) sacc[j] = make_float4(0.f, 0.f, 0.f, 0.f);

        #pragma unroll
        for (int ks = 0; ks < 4; ks++) {
            const int cb = ks * 8 + tig;
            const int r0 = (warp * 16 + g) * AST, r1 = r0 + 8 * AST;
            uint32_t ah0 = Qh[r0 + cb],     ah1 = Qh[r1 + cb];
            uint32_t ah2 = Qh[r0 + cb + 4], ah3 = Qh[r1 + cb + 4];
            uint32_t al0 = Ql[r0 + cb],     al1 = Ql[r1 + cb];
            uint32_t al2 = Ql[r0 + cb + 4], al3 = Ql[r1 + cb + 4];
            #pragma unroll
            for (int jn = 0; jn < 8; jn++) {
                int n = (jn * 8 + g) * AST;
                uint32_t bh0 = Kh[n + cb], bh1 = Kh[n + cb + 4];
                uint32_t bl0 = Kl[n + cb], bl1 = Kl[n + cb + 4];
                mma_bf16(sacc[jn], ah0, ah1, ah2, ah3, bh0, bh1);
                mma_bf16(sacc[jn], ah0, ah1, ah2, ah3, bl0, bl1);
                mma_bf16(sacc[jn], al0, al1, al2, al3, bh0, bh1);
            }
        }

        // ---- scale + mask ----
        const size_t mrow0 = ((size_t)b * S_ + qb + g) * S_ + kt;
        const size_t mrow1 = mrow0 + 8 * S_;
        #pragma unroll
        for (int jn = 0; jn < 8; jn++) {
            int kc = jn * 8 + 2 * tig;
            int2 m0 = *reinterpret_cast<const int2*>(mask + mrow0 + kc);
            int2 m1 = *reinterpret_cast<const int2*>(mask + mrow1 + kc);
            sacc[jn].x = m0.x ? sacc[jn].x * 0.125f : -1e9f;
            sacc[jn].y = m0.y ? sacc[jn].y * 0.125f : -1e9f;
            sacc[jn].z = m1.x ? sacc[jn].z * 0.125f : -1e9f;
            sacc[jn].w = m1.y ? sacc[jn].w * 0.125f : -1e9f;
        }

        // ---- online softmax (rows g and g+8) ----
        float rm0 = -1e30f, rm1 = -1e30f;
        #pragma unroll
        for (int jn = 0; jn < 8; jn++) {
            rm0 = fmaxf(rm0, fmaxf(sacc[jn].x, sacc[jn].y));
            rm1 = fmaxf(rm1, fmaxf(sacc[jn].z, sacc[jn].w));
        }
        rm0 = fmaxf(rm0, __shfl_xor_sync(0xffffffffu, rm0, 1));
        rm0 = fmaxf(rm0, __shfl_xor_sync(0xffffffffu, rm0, 2));
        rm1 = fmaxf(rm1, __shfl_xor_sync(0xffffffffu, rm1, 1));
        rm1 = fmaxf(rm1, __shfl_xor_sync(0xffffffffu, rm1, 2));

        float mnew0 = fmaxf(mrun0, rm0), mnew1 = fmaxf(mrun1, rm1);
        float corr0 = fexp(mrun0 - mnew0), corr1 = fexp(mrun1 - mnew1);
        #pragma unroll
        for (int dn = 0; dn < 8; dn++) {
            oacc[dn].x *= corr0; oacc[dn].y *= corr0;
            oacc[dn].z *= corr1; oacc[dn].w *= corr1;
        }
        float ls0 = 0.f, ls1 = 0.f;
        #pragma unroll
        for (int jn = 0; jn < 8; jn++) {
            sacc[jn].x = fexp(sacc[jn].x - mnew0);
            sacc[jn].y = fexp(sacc[jn].y - mnew0);
            sacc[jn].z = fexp(sacc[jn].z - mnew1);
            sacc[jn].w = fexp(sacc[jn].w - mnew1);
            ls0 += sacc[jn].x + sacc[jn].y;
            ls1 += sacc[jn].z + sacc[jn].w;
        }
        ls0 += __shfl_xor_sync(0xffffffffu, ls0, 1);
        ls0 += __shfl_xor_sync(0xffffffffu, ls0, 2);
        ls1 += __shfl_xor_sync(0xffffffffu, ls1, 1);
        ls1 += __shfl_xor_sync(0xffffffffu, ls1, 2);
        lrun0 = lrun0 * corr0 + ls0;
        lrun1 = lrun1 * corr1 + ls1;
        mrun0 = mnew0; mrun1 = mnew1;

        // ---- phase 2: O += P V (P frags from registers, bf16x3) ----
        #pragma unroll
        for (int t = 0; t < 4; t++) {
            const float4 p0 = sacc[2 * t], p1 = sacc[2 * t + 1];
            __nv_bfloat16 h0x = __float2bfloat16(p0.x), h0y = __float2bfloat16(p0.y);
            __nv_bfloat16 h0z = __float2bfloat16(p0.z), h0w = __float2bfloat16(p0.w);
            __nv_bfloat16 h1x = __float2bfloat16(p1.x), h1y = __float2bfloat16(p1.y);
            __nv_bfloat16 h1z = __float2bfloat16(p1.z), h1w = __float2bfloat16(p1.w);
            uint32_t aph0 = pack_bf16(h0x, h0y);      // row g,   keys 16t+2tig..
            uint32_t aph1 = pack_bf16(h0z, h0w);      // row g+8
            uint32_t aph2 = pack_bf16(h1x, h1y);      // row g,   keys +8
            uint32_t aph3 = pack_bf16(h1z, h1w);      // row g+8
            uint32_t apl0 = pack_bf16(
                __float2bfloat16(p0.x - __bfloat162float(h0x)),
                __float2bfloat16(p0.y - __bfloat162float(h0y)));
            uint32_t apl1 = pack_bf16(
                __float2bfloat16(p0.z - __bfloat162float(h0z)),
                __float2bfloat16(p0.w - __bfloat162float(h0w)));
            uint32_t apl2 = pack_bf16(
                __float2bfloat16(p1.x - __bfloat162float(h1x)),
                __float2bfloat16(p1.y - __bfloat162float(h1y)));
            uint32_t apl3 = pack_bf16(
                __float2bfloat16(p1.z - __bfloat162float(h1z)),
                __float2bfloat16(p1.w - __bfloat162float(h1w)));
            #pragma unroll
            for (int dn = 0; dn < 8; dn++) {
                int nb = (dn * 8 + g) * AST + t * 8 + tig;
                uint32_t bvh0 = Vth[nb], bvh1 = Vth[nb + 4];
                uint32_t bvl0 = Vtl[nb], bvl1 = Vtl[nb + 4];
                mma_bf16(oacc[dn], aph0, aph1, aph2, aph3, bvh0, bvh1);
                mma_bf16(oacc[dn], aph0, aph1, aph2, aph3, bvl0, bvl1);
                mma_bf16(oacc[dn], apl0, apl1, apl2, apl3, bvh0, bvh1);
            }
        }
    }

    // ---- finalize: normalize and write ----
    const float inv0 = 1.f / lrun0, inv1 = 1.f / lrun1;
    float* o0 = O + ((size_t)b * S_ + qb + g) * D_ + h * DK_;
    float* o1 = o0 + 8 * D_;
    #pragma unroll
    for (int dn = 0; dn < 8; dn++) {
        int c = dn * 8 + 2 * tig;
        *reinterpret_cast<float2*>(o0 + c) =
            make_float2(oacc[dn].x * inv0, oacc[dn].y * inv0);
        *reinterpret_cast<float2*>(o1 + c) =
            make_float2(oacc[dn].z * inv1, oacc[dn].w * inv1);
    }
}

// ---------------------------------------------------------------------------
// Launch: 5 kernels, graph-capturable, no allocations / syncs.
// ---------------------------------------------------------------------------
extern "C" void kernel_launch(void* const* d_in, const int* in_sizes, int n_in,
                              void* d_out, int out_size)
{
    const float* q    = (const float*)d_in[0];
    const float* k    = (const float*)d_in[1];
    const float* v    = (const float*)d_in[2];
    const int*   mask = (const int*)  d_in[3];
    const float* w_q  = (const float*)d_in[4];
    const float* w_k  = (const float*)d_in[5];
    const float* w_v  = (const float*)d_in[6];
    const float* w_o  = (const float*)d_in[7];
    float* out = (float*)d_out;

    float *gq, *gk, *gv, *ga;
    cudaGetSymbolAddress((void**)&gq, g_Q);
    cudaGetSymbolAddress((void**)&gk, g_K);
    cudaGetSymbolAddress((void**)&gv, g_V);
    cudaGetSymbolAddress((void**)&ga, g_A);

    const int M = B_ * S_;                 // 8192
    dim3 gemm_grid(D_ / 128, M / 128);     // (8, 64)

    const int gemm_smem = 4 * BUF * (int)sizeof(uint32_t);   // 73728 B
    cudaFuncSetAttribute(gemm_bf16_kernel,
                         cudaFuncAttributeMaxDynamicSharedMemorySize, gemm_smem);

    gemm_bf16_kernel<<<gemm_grid, 256, gemm_smem>>>(q, w_q, gq, M, D_, D_);
    gemm_bf16_kernel<<<gemm_grid, 256, gemm_smem>>>(k, w_k, gk, M, D_, D_);
    gemm_bf16_kernel<<<gemm_grid, 256, gemm_smem>>>(v, w_v, gv, M, D_, D_);

    const int attn_smem = ATOT * (int)sizeof(uint32_t);      // 73728 B
    cudaFuncSetAttribute(attn_mma_kernel,
                         cudaFuncAttributeMaxDynamicSharedMemorySize, attn_smem);
    dim3 attn_grid(S_ / 128, B_ * H_);     // (16, 64)
    attn_mma_kernel<<<attn_grid, 256, attn_smem>>>(gq, gk, gv, mask, ga);

    gemm_bf16_kernel<<<gemm_grid, 256, gemm_smem>>>(ga, w_o, out, M, D_, D_);
}

// round 13
// speedup vs baseline: 4.0773x; 1.1240x over previous
#include <cuda_runtime.h>
#include <cuda_bf16.h>
#include <cstdint>

#define B_  4
#define S_  2048
#define D_  1024
#define H_  16
#define DK_ 64

// Scratch (no cudaMalloc allowed; __device__ globals are the workaround).
__device__ float g_Q[(size_t)B_ * S_ * D_];
__device__ float g_K[(size_t)B_ * S_ * D_];
__device__ float g_V[(size_t)B_ * S_ * D_];
__device__ float g_A[(size_t)B_ * S_ * D_];

// ===========================================================================
// Common helpers
// ===========================================================================
__device__ __forceinline__ uint32_t smem_u32(const void* p)
{
    uint32_t a;
    asm("{ .reg .u64 t; cvta.to.shared.u64 t, %1; cvt.u32.u64 %0, t; }"
        : "=r"(a) : "l"(p));
    return a;
}

__device__ __forceinline__ uint32_t pack_bf16(__nv_bfloat16 a, __nv_bfloat16 b)
{
    return (uint32_t)__bfloat16_as_ushort(a) |
           ((uint32_t)__bfloat16_as_ushort(b) << 16);
}

__device__ __forceinline__ void split_store(uint32_t* hi, uint32_t* lo,
                                            int base, float4 v)
{
    __nv_bfloat16 hx = __float2bfloat16(v.x), hy = __float2bfloat16(v.y);
    __nv_bfloat16 hz = __float2bfloat16(v.z), hw = __float2bfloat16(v.w);
    *reinterpret_cast<uint2*>(hi + base) =
        make_uint2(pack_bf16(hx, hy), pack_bf16(hz, hw));
    __nv_bfloat16 lx = __float2bfloat16(v.x - __bfloat162float(hx));
    __nv_bfloat16 ly = __float2bfloat16(v.y - __bfloat162float(hy));
    __nv_bfloat16 lz = __float2bfloat16(v.z - __bfloat162float(hz));
    __nv_bfloat16 lw = __float2bfloat16(v.w - __bfloat162float(hw));
    *reinterpret_cast<uint2*>(lo + base) =
        make_uint2(pack_bf16(lx, ly), pack_bf16(lz, lw));
}

__device__ __forceinline__ void mma_bf16(float4& c,
    uint32_t a0, uint32_t a1, uint32_t a2, uint32_t a3,
    uint32_t b0, uint32_t b1)
{
    asm volatile(
        "mma.sync.aligned.m16n8k16.row.col.f32.bf16.bf16.f32 "
        "{%0,%1,%2,%3}, {%4,%5,%6,%7}, {%8,%9}, {%0,%1,%2,%3};"
        : "+f"(c.x), "+f"(c.y), "+f"(c.z), "+f"(c.w)
        : "r"(a0), "r"(a1), "r"(a2), "r"(a3), "r"(b0), "r"(b1));
}

// ldmatrix x4: lanes 0-7/8-15/16-23/24-31 address the 4 8x8 b16 tiles.
__device__ __forceinline__ void ldm_x4(uint32_t& r0, uint32_t& r1,
                                       uint32_t& r2, uint32_t& r3, uint32_t a)
{
    asm volatile(
        "ldmatrix.sync.aligned.m8n8.x4.shared.b16 {%0,%1,%2,%3}, [%4];"
        : "=r"(r0), "=r"(r1), "=r"(r2), "=r"(r3) : "r"(a));
}

// Fast exp on the FMA pipe (no MUFU): 2^x range reduction + deg-5 poly.
__device__ __forceinline__ float fexp(float x)
{
    float t = fmaxf(x * 1.4426950408889634f, -126.0f);
    float z = t + 12582912.0f;               // 1.5 * 2^23
    int  ei = __float_as_int(z) - 0x4B400000;
    float f = t - (z - 12582912.0f);         // f in [-0.5, 0.5]
    float p = fmaf(0.0013333558f, f, 0.0096181291f);
    p = fmaf(p, f, 0.0555041087f);
    p = fmaf(p, f, 0.2402265069f);
    p = fmaf(p, f, 0.6931471806f);
    p = fmaf(p, f, 1.0f);
    return __int_as_float(__float_as_int(p) + (ei << 23));
}

// Per-lane ldmatrix address offsets (bytes), layout row stride AST u32.
// A-style (m16k16): lane -> row (lane&15), k-half (lane>>4).
// B-style (two n8k16 tiles): lane -> row (lane&7) + (lane>>4)*8,
//                            k-half (lane>>3)&1.
#define AST 36
__device__ __forceinline__ uint32_t a_off(int lane)
{
    return (uint32_t)(((lane & 15) * AST + (lane >> 4) * 4) * 4);
}
__device__ __forceinline__ uint32_t b_off(int lane)
{
    return (uint32_t)((((lane & 7) + ((lane >> 4) << 3)) * AST +
                       ((lane >> 3) & 1) * 4) * 4);
}

// ===========================================================================
// bf16x3 tensor-core GEMM with ldmatrix fragment loads.
// C[M,N] = A[M,K] * B[N,K]^T;  C += Ah*Bh + Ah*Bl + Al*Bh.
// BM=BN=128, BK=64, 256 thr = 8 warps (2m x 4n). 73728 B smem -> 2 CTAs/SM.
// ===========================================================================
#define GBK 64
#define BUF (128 * AST)

__global__ void __launch_bounds__(256, 2)
gemm_bf16_kernel(const float* __restrict__ A, const float* __restrict__ Bm,
                 float* __restrict__ C, int M, int N, int Kd)
{
    extern __shared__ uint32_t smu[];
    uint32_t* Ah = smu;
    uint32_t* Al = smu + BUF;
    uint32_t* Bh = smu + 2 * BUF;
    uint32_t* Bl = smu + 3 * BUF;

    const uint32_t sb   = smem_u32(smu);
    const uint32_t sbAh = sb;
    const uint32_t sbAl = sb + BUF * 4;
    const uint32_t sbBh = sb + 2 * BUF * 4;
    const uint32_t sbBl = sb + 3 * BUF * 4;

    const int tid  = threadIdx.x;
    const int lane = tid & 31;
    const int warp = tid >> 5;
    const int g    = lane >> 2;
    const int tig  = lane & 3;
    const int wm   = (warp >> 2) * 64;
    const int wn   = (warp & 3) * 32;
    const int m0   = blockIdx.y * 128;
    const int n0   = blockIdx.x * 128;
    const uint32_t ao = a_off(lane);
    const uint32_t bo = b_off(lane);

    float4 acc[4][4];
    #pragma unroll
    for (int i = 0; i < 4; i++)
        #pragma unroll
        for (int j = 0; j < 4; j++) acc[i][j] = make_float4(0.f, 0.f, 0.f, 0.f);

    for (int k0 = 0; k0 < D_; k0 += GBK) {
        __syncthreads();
        #pragma unroll
        for (int i = 0; i < 8; i++) {
            int idx = tid + i * 256;
            int r = idx >> 4, c4 = (idx & 15) * 4;
            int base = r * AST + (c4 >> 1);
            float4 va = *reinterpret_cast<const float4*>(
                A + (size_t)(m0 + r) * D_ + k0 + c4);
            split_store(Ah, Al, base, va);
            float4 vb = *reinterpret_cast<const float4*>(
                Bm + (size_t)(n0 + r) * D_ + k0 + c4);
            split_store(Bh, Bl, base, vb);
        }
        __syncthreads();

        #pragma unroll
        for (int ks = 0; ks < GBK / 16; ks++) {
            uint32_t bh[4][2], bl[4][2];
            #pragma unroll
            for (int tp = 0; tp < 2; tp++) {
                uint32_t ba = (uint32_t)(((wn + tp * 16) * AST + ks * 8) * 4) + bo;
                ldm_x4(bh[2 * tp][0], bh[2 * tp][1],
                       bh[2 * tp + 1][0], bh[2 * tp + 1][1], sbBh + ba);
                ldm_x4(bl[2 * tp][0], bl[2 * tp][1],
                       bl[2 * tp + 1][0], bl[2 * tp + 1][1], sbBl + ba);
            }
            #pragma unroll
            for (int tm = 0; tm < 4; tm++) {
                uint32_t aa = (uint32_t)(((wm + tm * 16) * AST + ks * 8) * 4) + ao;
                uint32_t ah0, ah1, ah2, ah3, al0, al1, al2, al3;
                ldm_x4(ah0, ah1, ah2, ah3, sbAh + aa);
                ldm_x4(al0, al1, al2, al3, sbAl + aa);
                #pragma unroll
                for (int tn = 0; tn < 4; tn++) {
                    mma_bf16(acc[tm][tn], ah0, ah1, ah2, ah3,
                             bh[tn][0], bh[tn][1]);
                    mma_bf16(acc[tm][tn], ah0, ah1, ah2, ah3,
                             bl[tn][0], bl[tn][1]);
                    mma_bf16(acc[tm][tn], al0, al1, al2, al3,
                             bh[tn][0], bh[tn][1]);
                }
            }
        }
    }

    #pragma unroll
    for (int tm = 0; tm < 4; tm++) {
        #pragma unroll
        for (int tn = 0; tn < 4; tn++) {
            int row = m0 + wm + tm * 16 + g;
            int col = n0 + wn + tn * 8 + 2 * tig;
            *reinterpret_cast<float2*>(C + (size_t)row * N + col) =
                make_float2(acc[tm][tn].x, acc[tm][tn].y);
            *reinterpret_cast<float2*>(C + (size_t)(row + 8) * N + col) =
                make_float2(acc[tm][tn].z, acc[tm][tn].w);
        }
    }
}

// ===========================================================================
// bf16x3 mma flash attention with ldmatrix fragment loads.
// Structure identical to R12 (measured 912 us); only fragment loads changed.
// ===========================================================================
#define AQH 0
#define AQL (128 * AST)          // 4608
#define AKH (2 * 128 * AST)      // 9216
#define AKL (AKH + 64 * AST)     // 11520
#define AVH (AKL + 64 * AST)     // 13824
#define AVL (AVH + 64 * AST)     // 16128
#define ATOT (AVL + 64 * AST)    // 18432 u32 = 73728 B

__global__ void __launch_bounds__(256, 2)
attn_mma_kernel(const float* __restrict__ Q, const float* __restrict__ Kt,
                const float* __restrict__ Vt, const int* __restrict__ mask,
                float* __restrict__ O)
{
    extern __shared__ uint32_t smu[];
    uint32_t* Qh  = smu + AQH;
    uint32_t* Ql  = smu + AQL;
    uint32_t* Kh  = smu + AKH;
    uint32_t* Kl  = smu + AKL;
    uint32_t* Vth = smu + AVH;
    uint32_t* Vtl = smu + AVL;

    const uint32_t sb   = smem_u32(smu);
    const uint32_t sbQh = sb + AQH * 4;
    const uint32_t sbQl = sb + AQL * 4;
    const uint32_t sbKh = sb + AKH * 4;
    const uint32_t sbKl = sb + AKL * 4;
    const uint32_t sbVh = sb + AVH * 4;
    const uint32_t sbVl = sb + AVL * 4;

    const int tid  = threadIdx.x;
    const int lane = tid & 31;
    const int warp = tid >> 5;           // 0..7
    const int g    = lane >> 2;          // 0..7
    const int tig  = lane & 3;           // 0..3
    const int b    = blockIdx.y >> 4;
    const int h    = blockIdx.y & 15;
    const int q0   = blockIdx.x * 128;
    const int qb   = q0 + warp * 16;
    const uint32_t ao = a_off(lane);
    const uint32_t bo = b_off(lane);

    // ---- stage Q tile [128 x 64] hi/lo (once) ----
    #pragma unroll
    for (int i = 0; i < 8; i++) {
        int idx = tid + i * 256;         // 0..2047
        int r = idx >> 4, c4 = (idx & 15) * 4;
        float4 v = *reinterpret_cast<const float4*>(
            Q + ((size_t)b * S_ + q0 + r) * D_ + h * DK_ + c4);
        split_store(Qh, Ql, r * AST + (c4 >> 1), v);
    }

    float4 oacc[8];
    #pragma unroll
    for (int i = 0; i < 8; i++) oacc[i] = make_float4(0.f, 0.f, 0.f, 0.f);
    float mrun0 = -1e30f, mrun1 = -1e30f, lrun0 = 0.f, lrun1 = 0.f;

    const int vp = tid & 31;             // key pair for V staging
    const int vd = (tid >> 5) * 8;       // d-group for V staging

    for (int kt = 0; kt < S_; kt += 64) {
        __syncthreads();                 // prior tile reads done
        // ---- stage K tile [64 keys x 64 d] hi/lo ----
        #pragma unroll
        for (int i = 0; i < 4; i++) {
            int idx = tid + i * 256;     // 0..1023
            int r = idx >> 4, c4 = (idx & 15) * 4;
            float4 v = *reinterpret_cast<const float4*>(
                Kt + ((size_t)b * S_ + kt + r) * D_ + h * DK_ + c4);
            split_store(Kh, Kl, r * AST + (c4 >> 1), v);
        }
        // ---- stage V^T [64 d x 64 keys] hi/lo, key pairs packed per u32 ----
        {
            const float* v0p = Vt + ((size_t)b * S_ + kt + 2 * vp) * D_ + h * DK_ + vd;
            const float* v1p = v0p + D_;
            float4 v0a = *reinterpret_cast<const float4*>(v0p);
            float4 v0b = *reinterpret_cast<const float4*>(v0p + 4);
            float4 v1a = *reinterpret_cast<const float4*>(v1p);
            float4 v1b = *reinterpret_cast<const float4*>(v1p + 4);
            const float* e0 = &v0a.x;
            const float* e1 = &v1a.x;
            #pragma unroll
            for (int j = 0; j < 8; j++) {
                float x0 = (j < 4) ? e0[j] : (&v0b.x)[j - 4];
                float x1 = (j < 4) ? e1[j] : (&v1b.x)[j - 4];
                __nv_bfloat16 h0 = __float2bfloat16(x0);
                __nv_bfloat16 h1 = __float2bfloat16(x1);
                Vth[(vd + j) * AST + vp] = pack_bf16(h0, h1);
                Vtl[(vd + j) * AST + vp] = pack_bf16(
                    __float2bfloat16(x0 - __bfloat162float(h0)),
                    __float2bfloat16(x1 - __bfloat162float(h1)));
            }
        }
        __syncthreads();

        // ---- phase 1: S = Q K^T (bf16x3, ldmatrix frags) ----
        float4 sacc[8];
        #pragma unroll
        for (int j = 0; j < 8; j++) sacc[j] = make_float4(0.f, 0.f, 0.f, 0.f);

        #pragma unroll
        for (int ks = 0; ks < 4; ks++) {
            uint32_t aa = (uint32_t)(((warp * 16) * AST + ks * 8) * 4) + ao;
            uint32_t ah0, ah1, ah2, ah3, al0, al1, al2, al3;
            ldm_x4(ah0, ah1, ah2, ah3, sbQh + aa);
            ldm_x4(al0, al1, al2, al3, sbQl + aa);
            #pragma unroll
            for (int jp = 0; jp < 4; jp++) {
                uint32_t ba = (uint32_t)(((jp * 16) * AST + ks * 8) * 4) + bo;
                uint32_t bh0, bh1, bh2, bh3, bl0, bl1, bl2, bl3;
                ldm_x4(bh0, bh1, bh2, bh3, sbKh + ba);
                ldm_x4(bl0, bl1, bl2, bl3, sbKl + ba);
                mma_bf16(sacc[2 * jp],     ah0, ah1, ah2, ah3, bh0, bh1);
                mma_bf16(sacc[2 * jp],     ah0, ah1, ah2, ah3, bl0, bl1);
                mma_bf16(sacc[2 * jp],     al0, al1, al2, al3, bh0, bh1);
                mma_bf16(sacc[2 * jp + 1], ah0, ah1, ah2, ah3, bh2, bh3);
                mma_bf16(sacc[2 * jp + 1], ah0, ah1, ah2, ah3, bl2, bl3);
                mma_bf16(sacc[2 * jp + 1], al0, al1, al2, al3, bh2, bh3);
            }
        }

        // ---- scale + mask ----
        const size_t mrow0 = ((size_t)b * S_ + qb + g) * S_ + kt;
        const size_t mrow1 = mrow0 + 8 * S_;
        #pragma unroll
        for (int jn = 0; jn < 8; jn++) {
            int kc = jn * 8 + 2 * tig;
            int2 m0 = *reinterpret_cast<const int2*>(mask + mrow0 + kc);
            int2 m1 = *reinterpret_cast<const int2*>(mask + mrow1 + kc);
            sacc[jn].x = m0.x ? sacc[jn].x * 0.125f : -1e9f;
            sacc[jn].y = m0.y ? sacc[jn].y * 0.125f : -1e9f;
            sacc[jn].z = m1.x ? sacc[jn].z * 0.125f : -1e9f;
            sacc[jn].w = m1.y ? sacc[jn].w * 0.125f : -1e9f;
        }

        // ---- online softmax (rows g and g+8) ----
        float rm0 = -1e30f, rm1 = -1e30f;
        #pragma unroll
        for (int jn = 0; jn < 8; jn++) {
            rm0 = fmaxf(rm0, fmaxf(sacc[jn].x, sacc[jn].y));
            rm1 = fmaxf(rm1, fmaxf(sacc[jn].z, sacc[jn].w));
        }
        rm0 = fmaxf(rm0, __shfl_xor_sync(0xffffffffu, rm0, 1));
        rm0 = fmaxf(rm0, __shfl_xor_sync(0xffffffffu, rm0, 2));
        rm1 = fmaxf(rm1, __shfl_xor_sync(0xffffffffu, rm1, 1));
        rm1 = fmaxf(rm1, __shfl_xor_sync(0xffffffffu, rm1, 2));

        float mnew0 = fmaxf(mrun0, rm0), mnew1 = fmaxf(mrun1, rm1);
        float corr0 = fexp(mrun0 - mnew0), corr1 = fexp(mrun1 - mnew1);
        #pragma unroll
        for (int dn = 0; dn < 8; dn++) {
            oacc[dn].x *= corr0; oacc[dn].y *= corr0;
            oacc[dn].z *= corr1; oacc[dn].w *= corr1;
        }
        float ls0 = 0.f, ls1 = 0.f;
        #pragma unroll
        for (int jn = 0; jn < 8; jn++) {
            sacc[jn].x = fexp(sacc[jn].x - mnew0);
            sacc[jn].y = fexp(sacc[jn].y - mnew0);
            sacc[jn].z = fexp(sacc[jn].z - mnew1);
            sacc[jn].w = fexp(sacc[jn].w - mnew1);
            ls0 += sacc[jn].x + sacc[jn].y;
            ls1 += sacc[jn].z + sacc[jn].w;
        }
        ls0 += __shfl_xor_sync(0xffffffffu, ls0, 1);
        ls0 += __shfl_xor_sync(0xffffffffu, ls0, 2);
        ls1 += __shfl_xor_sync(0xffffffffu, ls1, 1);
        ls1 += __shfl_xor_sync(0xffffffffu, ls1, 2);
        lrun0 = lrun0 * corr0 + ls0;
        lrun1 = lrun1 * corr1 + ls1;
        mrun0 = mnew0; mrun1 = mnew1;

        // ---- phase 2: O += P V (P frags from registers, ldmatrix V) ----
        #pragma unroll
        for (int t = 0; t < 4; t++) {
            const float4 p0 = sacc[2 * t], p1 = sacc[2 * t + 1];
            __nv_bfloat16 h0x = __float2bfloat16(p0.x), h0y = __float2bfloat16(p0.y);
            __nv_bfloat16 h0z = __float2bfloat16(p0.z), h0w = __float2bfloat16(p0.w);
            __nv_bfloat16 h1x = __float2bfloat16(p1.x), h1y = __float2bfloat16(p1.y);
            __nv_bfloat16 h1z = __float2bfloat16(p1.z), h1w = __float2bfloat16(p1.w);
            uint32_t aph0 = pack_bf16(h0x, h0y);
            uint32_t aph1 = pack_bf16(h0z, h0w);
            uint32_t aph2 = pack_bf16(h1x, h1y);
            uint32_t aph3 = pack_bf16(h1z, h1w);
            uint32_t apl0 = pack_bf16(
                __float2bfloat16(p0.x - __bfloat162float(h0x)),
                __float2bfloat16(p0.y - __bfloat162float(h0y)));
            uint32_t apl1 = pack_bf16(
                __float2bfloat16(p0.z - __bfloat162float(h0z)),
                __float2bfloat16(p0.w - __bfloat162float(h0w)));
            uint32_t apl2 = pack_bf16(
                __float2bfloat16(p1.x - __bfloat162float(h1x)),
                __float2bfloat16(p1.y - __bfloat162float(h1y)));
            uint32_t apl3 = pack_bf16(
                __float2bfloat16(p1.z - __bfloat162float(h1z)),
                __float2bfloat16(p1.w - __bfloat162float(h1w)));
            #pragma unroll
            for (int dp = 0; dp < 4; dp++) {
                uint32_t ba = (uint32_t)(((dp * 16) * AST + t * 8) * 4) + bo;
                uint32_t vh0, vh1, vh2, vh3, vl0, vl1, vl2, vl3;
                ldm_x4(vh0, vh1, vh2, vh3, sbVh + ba);
                ldm_x4(vl0, vl1, vl2, vl3, sbVl + ba);
                mma_bf16(oacc[2 * dp],     aph0, aph1, aph2, aph3, vh0, vh1);
                mma_bf16(oacc[2 * dp],     aph0, aph1, aph2, aph3, vl0, vl1);
                mma_bf16(oacc[2 * dp],     apl0, apl1, apl2, apl3, vh0, vh1);
                mma_bf16(oacc[2 * dp + 1], aph0, aph1, aph2, aph3, vh2, vh3);
                mma_bf16(oacc[2 * dp + 1], aph0, aph1, aph2, aph3, vl2, vl3);
                mma_bf16(oacc[2 * dp + 1], apl0, apl1, apl2, apl3, vh2, vh3);
            }
        }
    }

    // ---- finalize: normalize and write ----
    const float inv0 = 1.f / lrun0, inv1 = 1.f / lrun1;
    float* o0 = O + ((size_t)b * S_ + qb + g) * D_ + h * DK_;
    float* o1 = o0 + 8 * D_;
    #pragma unroll
    for (int dn = 0; dn < 8; dn++) {
        int c = dn * 8 + 2 * tig;
        *reinterpret_cast<float2*>(o0 + c) =
            make_float2(oacc[dn].x * inv0, oacc[dn].y * inv0);
        *reinterpret_cast<float2*>(o1 + c) =
            make_float2(oacc[dn].z * inv1, oacc[dn].w * inv1);
    }
}

// ---------------------------------------------------------------------------
// Launch: 5 kernels, graph-capturable, no allocations / syncs.
// ---------------------------------------------------------------------------
extern "C" void kernel_launch(void* const* d_in, const int* in_sizes, int n_in,
                              void* d_out, int out_size)
{
    const float* q    = (const float*)d_in[0];
    const float* k    = (const float*)d_in[1];
    const float* v    = (const float*)d_in[2];
    const int*   mask = (const int*)  d_in[3];
    const float* w_q  = (const float*)d_in[4];
    const float* w_k  = (const float*)d_in[5];
    const float* w_v  = (const float*)d_in[6];
    const float* w_o  = (const float*)d_in[7];
    float* out = (float*)d_out;

    float *gq, *gk, *gv, *ga;
    cudaGetSymbolAddress((void**)&gq, g_Q);
    cudaGetSymbolAddress((void**)&gk, g_K);
    cudaGetSymbolAddress((void**)&gv, g_V);
    cudaGetSymbolAddress((void**)&ga, g_A);

    const int M = B_ * S_;                 // 8192
    dim3 gemm_grid(D_ / 128, M / 128);     // (8, 64)

    const int gemm_smem = 4 * BUF * (int)sizeof(uint32_t);   // 73728 B
    cudaFuncSetAttribute(gemm_bf16_kernel,
                         cudaFuncAttributeMaxDynamicSharedMemorySize, gemm_smem);

    gemm_bf16_kernel<<<gemm_grid, 256, gemm_smem>>>(q, w_q, gq, M, D_, D_);
    gemm_bf16_kernel<<<gemm_grid, 256, gemm_smem>>>(k, w_k, gk, M, D_, D_);
    gemm_bf16_kernel<<<gemm_grid, 256, gemm_smem>>>(v, w_v, gv, M, D_, D_);

    const int attn_smem = ATOT * (int)sizeof(uint32_t);      // 73728 B
    cudaFuncSetAttribute(attn_mma_kernel,
                         cudaFuncAttributeMaxDynamicSharedMemorySize, attn_smem);
    dim3 attn_grid(S_ / 128, B_ * H_);     // (16, 64)
    attn_mma_kernel<<<attn_grid, 256, attn_smem>>>(gq, gk, gv, mask, ga);

    gemm_bf16_kernel<<<gemm_grid, 256, gemm_smem>>>(ga, w_o, out, M, D_, D_);
}

// round 14
// speedup vs baseline: 4.1173x; 1.0098x over previous
#include <cuda_runtime.h>
#include <cuda_bf16.h>
#include <cstdint>

#define B_  4
#define S_  2048
#define D_  1024
#define H_  16
#define DK_ 64
#define DP_ 512   // D/2 packed u32 per row

// Scratch (no cudaMalloc; __device__ globals). Split bf16 hi/lo Q/K/V + fp32 attn out.
__device__ uint32_t g_Qh[(size_t)B_ * S_ * DP_];
__device__ uint32_t g_Ql[(size_t)B_ * S_ * DP_];
__device__ uint32_t g_Kh[(size_t)B_ * S_ * DP_];
__device__ uint32_t g_Kl[(size_t)B_ * S_ * DP_];
__device__ uint32_t g_Vh[(size_t)B_ * S_ * DP_];
__device__ uint32_t g_Vl[(size_t)B_ * S_ * DP_];
__device__ float    g_A [(size_t)B_ * S_ * D_];

// ===========================================================================
// Common helpers
// ===========================================================================
__device__ __forceinline__ uint32_t smem_u32(const void* p)
{
    uint32_t a;
    asm("{ .reg .u64 t; cvta.to.shared.u64 t, %1; cvt.u32.u64 %0, t; }"
        : "=r"(a) : "l"(p));
    return a;
}

__device__ __forceinline__ uint32_t pack_bf16(__nv_bfloat16 a, __nv_bfloat16 b)
{
    return (uint32_t)__bfloat16_as_ushort(a) |
           ((uint32_t)__bfloat16_as_ushort(b) << 16);
}

__device__ __forceinline__ void split_store(uint32_t* hi, uint32_t* lo,
                                            int base, float4 v)
{
    __nv_bfloat16 hx = __float2bfloat16(v.x), hy = __float2bfloat16(v.y);
    __nv_bfloat16 hz = __float2bfloat16(v.z), hw = __float2bfloat16(v.w);
    *reinterpret_cast<uint2*>(hi + base) =
        make_uint2(pack_bf16(hx, hy), pack_bf16(hz, hw));
    __nv_bfloat16 lx = __float2bfloat16(v.x - __bfloat162float(hx));
    __nv_bfloat16 ly = __float2bfloat16(v.y - __bfloat162float(hy));
    __nv_bfloat16 lz = __float2bfloat16(v.z - __bfloat162float(hz));
    __nv_bfloat16 lw = __float2bfloat16(v.w - __bfloat162float(hw));
    *reinterpret_cast<uint2*>(lo + base) =
        make_uint2(pack_bf16(lx, ly), pack_bf16(lz, lw));
}

__device__ __forceinline__ void mma_bf16(float4& c,
    uint32_t a0, uint32_t a1, uint32_t a2, uint32_t a3,
    uint32_t b0, uint32_t b1)
{
    asm volatile(
        "mma.sync.aligned.m16n8k16.row.col.f32.bf16.bf16.f32 "
        "{%0,%1,%2,%3}, {%4,%5,%6,%7}, {%8,%9}, {%0,%1,%2,%3};"
        : "+f"(c.x), "+f"(c.y), "+f"(c.z), "+f"(c.w)
        : "r"(a0), "r"(a1), "r"(a2), "r"(a3), "r"(b0), "r"(b1));
}

__device__ __forceinline__ void ldm_x4(uint32_t& r0, uint32_t& r1,
                                       uint32_t& r2, uint32_t& r3, uint32_t a)
{
    asm volatile(
        "ldmatrix.sync.aligned.m8n8.x4.shared.b16 {%0,%1,%2,%3}, [%4];"
        : "=r"(r0), "=r"(r1), "=r"(r2), "=r"(r3) : "r"(a));
}

__device__ __forceinline__ void ldm_x4_t(uint32_t& r0, uint32_t& r1,
                                         uint32_t& r2, uint32_t& r3, uint32_t a)
{
    asm volatile(
        "ldmatrix.sync.aligned.m8n8.x4.trans.shared.b16 {%0,%1,%2,%3}, [%4];"
        : "=r"(r0), "=r"(r1), "=r"(r2), "=r"(r3) : "r"(a));
}

__device__ __forceinline__ void cpa16(uint32_t dst, const void* src)
{
    asm volatile("cp.async.ca.shared.global [%0], [%1], 16;"
                 :: "r"(dst), "l"(src) : "memory");
}

// Fast exp on the FMA pipe (no MUFU).
__device__ __forceinline__ float fexp(float x)
{
    float t = fmaxf(x * 1.4426950408889634f, -126.0f);
    float z = t + 12582912.0f;
    int  ei = __float_as_int(z) - 0x4B400000;
    float f = t - (z - 12582912.0f);
    float p = fmaf(0.0013333558f, f, 0.0096181291f);
    p = fmaf(p, f, 0.0555041087f);
    p = fmaf(p, f, 0.2402265069f);
    p = fmaf(p, f, 0.6931471806f);
    p = fmaf(p, f, 1.0f);
    return __int_as_float(__float_as_int(p) + (ei << 23));
}

#define AST 36
__device__ __forceinline__ uint32_t a_off(int lane)
{
    return (uint32_t)(((lane & 15) * AST + (lane >> 4) * 4) * 4);
}
__device__ __forceinline__ uint32_t b_off(int lane)
{
    return (uint32_t)((((lane & 7) + ((lane >> 4) << 3)) * AST +
                       ((lane >> 3) & 1) * 4) * 4);
}
// trans source: group -> (key-half (lane>>3)&1, d-block lane>>4); row = key.
__device__ __forceinline__ uint32_t v_off(int lane)
{
    return (uint32_t)(((lane & 15) * AST + (lane >> 4) * 4) * 4);
}

// ===========================================================================
// bf16x3 tensor-core GEMM, ldmatrix frags. SPLIT epilogue writes packed
// hi/lo bf16 u32 (for Q/K/V); else fp32.
// ===========================================================================
#define GBK 64
#define BUF (128 * AST)

template<bool SPLIT>
__global__ void __launch_bounds__(256, 2)
gemm_bf16_kernel(const float* __restrict__ A, const float* __restrict__ Bm,
                 float* __restrict__ C, uint32_t* __restrict__ Chi,
                 uint32_t* __restrict__ Clo, int M, int N)
{
    extern __shared__ uint32_t smu[];
    uint32_t* Ah = smu;
    uint32_t* Al = smu + BUF;
    uint32_t* Bh = smu + 2 * BUF;
    uint32_t* Bl = smu + 3 * BUF;

    const uint32_t sb   = smem_u32(smu);
    const uint32_t sbAh = sb;
    const uint32_t sbAl = sb + BUF * 4;
    const uint32_t sbBh = sb + 2 * BUF * 4;
    const uint32_t sbBl = sb + 3 * BUF * 4;

    const int tid  = threadIdx.x;
    const int lane = tid & 31;
    const int warp = tid >> 5;
    const int g    = lane >> 2;
    const int tig  = lane & 3;
    const int wm   = (warp >> 2) * 64;
    const int wn   = (warp & 3) * 32;
    const int m0   = blockIdx.y * 128;
    const int n0   = blockIdx.x * 128;
    const uint32_t ao = a_off(lane);
    const uint32_t bo = b_off(lane);

    float4 acc[4][4];
    #pragma unroll
    for (int i = 0; i < 4; i++)
        #pragma unroll
        for (int j = 0; j < 4; j++) acc[i][j] = make_float4(0.f, 0.f, 0.f, 0.f);

    for (int k0 = 0; k0 < D_; k0 += GBK) {
        __syncthreads();
        #pragma unroll
        for (int i = 0; i < 8; i++) {
            int idx = tid + i * 256;
            int r = idx >> 4, c4 = (idx & 15) * 4;
            int base = r * AST + (c4 >> 1);
            float4 va = *reinterpret_cast<const float4*>(
                A + (size_t)(m0 + r) * D_ + k0 + c4);
            split_store(Ah, Al, base, va);
            float4 vb = *reinterpret_cast<const float4*>(
                Bm + (size_t)(n0 + r) * D_ + k0 + c4);
            split_store(Bh, Bl, base, vb);
        }
        __syncthreads();

        #pragma unroll
        for (int ks = 0; ks < GBK / 16; ks++) {
            uint32_t bh[4][2], bl[4][2];
            #pragma unroll
            for (int tp = 0; tp < 2; tp++) {
                uint32_t ba = (uint32_t)(((wn + tp * 16) * AST + ks * 8) * 4) + bo;
                ldm_x4(bh[2 * tp][0], bh[2 * tp][1],
                       bh[2 * tp + 1][0], bh[2 * tp + 1][1], sbBh + ba);
                ldm_x4(bl[2 * tp][0], bl[2 * tp][1],
                       bl[2 * tp + 1][0], bl[2 * tp + 1][1], sbBl + ba);
            }
            #pragma unroll
            for (int tm = 0; tm < 4; tm++) {
                uint32_t aa = (uint32_t)(((wm + tm * 16) * AST + ks * 8) * 4) + ao;
                uint32_t ah0, ah1, ah2, ah3, al0, al1, al2, al3;
                ldm_x4(ah0, ah1, ah2, ah3, sbAh + aa);
                ldm_x4(al0, al1, al2, al3, sbAl + aa);
                #pragma unroll
                for (int tn = 0; tn < 4; tn++) {
                    mma_bf16(acc[tm][tn], ah0, ah1, ah2, ah3,
                             bh[tn][0], bh[tn][1]);
                    mma_bf16(acc[tm][tn], ah0, ah1, ah2, ah3,
                             bl[tn][0], bl[tn][1]);
                    mma_bf16(acc[tm][tn], al0, al1, al2, al3,
                             bh[tn][0], bh[tn][1]);
                }
            }
        }
    }

    #pragma unroll
    for (int tm = 0; tm < 4; tm++) {
        #pragma unroll
        for (int tn = 0; tn < 4; tn++) {
            int row = m0 + wm + tm * 16 + g;
            int col = n0 + wn + tn * 8 + 2 * tig;
            if (SPLIT) {
                // pack (c.x,c.y) -> one u32 pair at colpair col/2
                float4 c4v = acc[tm][tn];
                size_t i0 = (size_t)row * DP_ + (col >> 1);
                size_t i1 = (size_t)(row + 8) * DP_ + (col >> 1);
                __nv_bfloat16 hx = __float2bfloat16(c4v.x);
                __nv_bfloat16 hy = __float2bfloat16(c4v.y);
                __nv_bfloat16 hz = __float2bfloat16(c4v.z);
                __nv_bfloat16 hw = __float2bfloat16(c4v.w);
                Chi[i0] = pack_bf16(hx, hy);
                Chi[i1] = pack_bf16(hz, hw);
                Clo[i0] = pack_bf16(
                    __float2bfloat16(c4v.x - __bfloat162float(hx)),
                    __float2bfloat16(c4v.y - __bfloat162float(hy)));
                Clo[i1] = pack_bf16(
                    __float2bfloat16(c4v.z - __bfloat162float(hz)),
                    __float2bfloat16(c4v.w - __bfloat162float(hw)));
            } else {
                *reinterpret_cast<float2*>(C + (size_t)row * N + col) =
                    make_float2(acc[tm][tn].x, acc[tm][tn].y);
                *reinterpret_cast<float2*>(C + (size_t)(row + 8) * N + col) =
                    make_float2(acc[tm][tn].z, acc[tm][tn].w);
            }
        }
    }
}

// ===========================================================================
// bf16x3 mma flash attention: pre-split inputs, cp.async double-buffered
// K/V staging, ldmatrix(.trans for V) fragment loads.
// smem (u32): Qh 4608 | Ql 4608 | 2 x [Kh 2304 | Kl 2304 | Vh 2304 | Vl 2304]
//  = 27648 u32 = 110592 B -> 2 CTAs/SM.
// ===========================================================================
#define TQH 0
#define TQL 4608
#define TB0 9216
#define TBSZ 9216        // per tile buffer (K h/l + V h/l)
#define ATOT 27648

__global__ void __launch_bounds__(256, 2)
attn_mma_kernel(const uint32_t* __restrict__ qh, const uint32_t* __restrict__ ql,
                const uint32_t* __restrict__ kh, const uint32_t* __restrict__ kl,
                const uint32_t* __restrict__ vh, const uint32_t* __restrict__ vl,
                const int* __restrict__ mask, float* __restrict__ O)
{
    extern __shared__ uint32_t smu[];
    const uint32_t sb = smem_u32(smu);

    const int tid  = threadIdx.x;
    const int lane = tid & 31;
    const int warp = tid >> 5;           // 0..7
    const int g    = lane >> 2;          // 0..7
    const int tig  = lane & 3;           // 0..3
    const int b    = blockIdx.y >> 4;
    const int h    = blockIdx.y & 15;
    const int q0   = blockIdx.x * 128;
    const int qb   = q0 + warp * 16;
    const uint32_t ao = a_off(lane);
    const uint32_t bo = b_off(lane);
    const uint32_t vo = v_off(lane);
    const size_t   bS = (size_t)b * S_;

    // ---- stage Q tile [128 rows x 32 u32] hi/lo (once, plain loads) ----
    #pragma unroll
    for (int i = 0; i < 8; i++) {
        int idx = tid + i * 256;         // 0..2047
        int hl = idx >> 10;              // 0 hi, 1 lo
        int rem = idx & 1023;
        int r = rem >> 3, c = rem & 7;   // r 0..127, c chunk 0..7
        const uint32_t* src = (hl ? ql : qh) +
            (bS + q0 + r) * DP_ + h * 32 + c * 4;
        uint4 v = *reinterpret_cast<const uint4*>(src);
        *reinterpret_cast<uint4*>(smu + (hl ? TQL : TQH) + r * AST + c * 4) = v;
    }

    // ---- cp.async staging of one K/V tile into buffer bb ----
    auto stage = [&](int kt, int bb) {
        const uint32_t tb = sb + (uint32_t)(TB0 + bb * TBSZ) * 4;
        #pragma unroll
        for (int i = 0; i < 8; i++) {
            int idx = tid + i * 256;     // 0..2047
            int tv  = idx >> 10;         // 0 K, 1 V
            int rem = idx & 1023;
            int hl  = rem >> 9;          // 0 hi, 1 lo
            int r   = (rem >> 3) & 63;
            int c   = rem & 7;
            const uint32_t* src = (tv ? (hl ? vl : vh) : (hl ? kl : kh)) +
                (bS + kt + r) * DP_ + h * 32 + c * 4;
            uint32_t dst = tb + (uint32_t)((tv * 2 + hl) * 2304 +
                                           r * AST + c * 4) * 4;
            cpa16(dst, src);
        }
    };

    float4 oacc[8];
    #pragma unroll
    for (int i = 0; i < 8; i++) oacc[i] = make_float4(0.f, 0.f, 0.f, 0.f);
    float mrun0 = -1e30f, mrun1 = -1e30f, lrun0 = 0.f, lrun1 = 0.f;

    stage(0, 0);
    asm volatile("cp.async.commit_group;" ::: "memory");
    int pb = 0;

    for (int kt = 0; kt < S_; kt += 64) {
        __syncthreads();                 // all reads of buffer pb^1 done
        const bool more = (kt + 64 < S_);
        if (more) {
            stage(kt + 64, pb ^ 1);
            asm volatile("cp.async.commit_group;" ::: "memory");
            asm volatile("cp.async.wait_group 1;" ::: "memory");
        } else {
            asm volatile("cp.async.wait_group 0;" ::: "memory");
        }
        __syncthreads();

        const uint32_t tb  = sb + (uint32_t)(TB0 + pb * TBSZ) * 4;
        const uint32_t kbh = tb;
        const uint32_t kbl = tb + 2304u * 4;
        const uint32_t vbh = tb + 4608u * 4;
        const uint32_t vbl = tb + 6912u * 4;

        // ---- phase 1: S = Q K^T ----
        float4 sacc[8];
        #pragma unroll
        for (int j = 0; j < 8; j++) sacc[j] = make_float4(0.f, 0.f, 0.f, 0.f);

        #pragma unroll
        for (int ks = 0; ks < 4; ks++) {
            uint32_t aa = (uint32_t)(((warp * 16) * AST + ks * 8) * 4) + ao;
            uint32_t ah0, ah1, ah2, ah3, al0, al1, al2, al3;
            ldm_x4(ah0, ah1, ah2, ah3, sb + TQH * 4 + aa);
            ldm_x4(al0, al1, al2, al3, sb + TQL * 4 + aa);
            #pragma unroll
            for (int jp = 0; jp < 4; jp++) {
                uint32_t ba = (uint32_t)(((jp * 16) * AST + ks * 8) * 4) + bo;
                uint32_t bh0, bh1, bh2, bh3, bl0, bl1, bl2, bl3;
                ldm_x4(bh0, bh1, bh2, bh3, kbh + ba);
                ldm_x4(bl0, bl1, bl2, bl3, kbl + ba);
                mma_bf16(sacc[2 * jp],     ah0, ah1, ah2, ah3, bh0, bh1);
                mma_bf16(sacc[2 * jp],     ah0, ah1, ah2, ah3, bl0, bl1);
                mma_bf16(sacc[2 * jp],     al0, al1, al2, al3, bh0, bh1);
                mma_bf16(sacc[2 * jp + 1], ah0, ah1, ah2, ah3, bh2, bh3);
                mma_bf16(sacc[2 * jp + 1], ah0, ah1, ah2, ah3, bl2, bl3);
                mma_bf16(sacc[2 * jp + 1], al0, al1, al2, al3, bh2, bh3);
            }
        }

        // ---- scale + mask ----
        const size_t mrow0 = (bS + qb + g) * S_ + kt;
        const size_t mrow1 = mrow0 + 8 * S_;
        #pragma unroll
        for (int jn = 0; jn < 8; jn++) {
            int kc = jn * 8 + 2 * tig;
            int2 m0 = *reinterpret_cast<const int2*>(mask + mrow0 + kc);
            int2 m1 = *reinterpret_cast<const int2*>(mask + mrow1 + kc);
            sacc[jn].x = m0.x ? sacc[jn].x * 0.125f : -1e9f;
            sacc[jn].y = m0.y ? sacc[jn].y * 0.125f : -1e9f;
            sacc[jn].z = m1.x ? sacc[jn].z * 0.125f : -1e9f;
            sacc[jn].w = m1.y ? sacc[jn].w * 0.125f : -1e9f;
        }

        // ---- online softmax (rows g and g+8) ----
        float rm0 = -1e30f, rm1 = -1e30f;
        #pragma unroll
        for (int jn = 0; jn < 8; jn++) {
            rm0 = fmaxf(rm0, fmaxf(sacc[jn].x, sacc[jn].y));
            rm1 = fmaxf(rm1, fmaxf(sacc[jn].z, sacc[jn].w));
        }
        rm0 = fmaxf(rm0, __shfl_xor_sync(0xffffffffu, rm0, 1));
        rm0 = fmaxf(rm0, __shfl_xor_sync(0xffffffffu, rm0, 2));
        rm1 = fmaxf(rm1, __shfl_xor_sync(0xffffffffu, rm1, 1));
        rm1 = fmaxf(rm1, __shfl_xor_sync(0xffffffffu, rm1, 2));

        float mnew0 = fmaxf(mrun0, rm0), mnew1 = fmaxf(mrun1, rm1);
        float corr0 = fexp(mrun0 - mnew0), corr1 = fexp(mrun1 - mnew1);
        #pragma unroll
        for (int dn = 0; dn < 8; dn++) {
            oacc[dn].x *= corr0; oacc[dn].y *= corr0;
            oacc[dn].z *= corr1; oacc[dn].w *= corr1;
        }
        float ls0 = 0.f, ls1 = 0.f;
        #pragma unroll
        for (int jn = 0; jn < 8; jn++) {
            sacc[jn].x = fexp(sacc[jn].x - mnew0);
            sacc[jn].y = fexp(sacc[jn].y - mnew0);
            sacc[jn].z = fexp(sacc[jn].z - mnew1);
            sacc[jn].w = fexp(sacc[jn].w - mnew1);
            ls0 += sacc[jn].x + sacc[jn].y;
            ls1 += sacc[jn].z + sacc[jn].w;
        }
        ls0 += __shfl_xor_sync(0xffffffffu, ls0, 1);
        ls0 += __shfl_xor_sync(0xffffffffu, ls0, 2);
        ls1 += __shfl_xor_sync(0xffffffffu, ls1, 1);
        ls1 += __shfl_xor_sync(0xffffffffu, ls1, 2);
        lrun0 = lrun0 * corr0 + ls0;
        lrun1 = lrun1 * corr1 + ls1;
        mrun0 = mnew0; mrun1 = mnew1;

        // ---- phase 2: O += P V (P frags from regs; V via ldmatrix.trans) ----
        #pragma unroll
        for (int t = 0; t < 4; t++) {
            const float4 p0 = sacc[2 * t], p1 = sacc[2 * t + 1];
            __nv_bfloat16 h0x = __float2bfloat16(p0.x), h0y = __float2bfloat16(p0.y);
            __nv_bfloat16 h0z = __float2bfloat16(p0.z), h0w = __float2bfloat16(p0.w);
            __nv_bfloat16 h1x = __float2bfloat16(p1.x), h1y = __float2bfloat16(p1.y);
            __nv_bfloat16 h1z = __float2bfloat16(p1.z), h1w = __float2bfloat16(p1.w);
            uint32_t aph0 = pack_bf16(h0x, h0y);
            uint32_t aph1 = pack_bf16(h0z, h0w);
            uint32_t aph2 = pack_bf16(h1x, h1y);
            uint32_t aph3 = pack_bf16(h1z, h1w);
            uint32_t apl0 = pack_bf16(
                __float2bfloat16(p0.x - __bfloat162float(h0x)),
                __float2bfloat16(p0.y - __bfloat162float(h0y)));
            uint32_t apl1 = pack_bf16(
                __float2bfloat16(p0.z - __bfloat162float(h0z)),
                __float2bfloat16(p0.w - __bfloat162float(h0w)));
            uint32_t apl2 = pack_bf16(
                __float2bfloat16(p1.x - __bfloat162float(h1x)),
                __float2bfloat16(p1.y - __bfloat162float(h1y)));
            uint32_t apl3 = pack_bf16(
                __float2bfloat16(p1.z - __bfloat162float(h1z)),
                __float2bfloat16(p1.w - __bfloat162float(h1w)));
            #pragma unroll
            for (int dp = 0; dp < 4; dp++) {
                // source rows = keys t*16 + (lane&15); cols = d-pairs dp*8 + ..
                uint32_t ba = (uint32_t)(((t * 16) * AST + dp * 8) * 4) + vo;
                uint32_t vh0, vh1, vh2, vh3, vl0, vl1, vl2, vl3;
                ldm_x4_t(vh0, vh1, vh2, vh3, vbh + ba);
                ldm_x4_t(vl0, vl1, vl2, vl3, vbl + ba);
                mma_bf16(oacc[2 * dp],     aph0, aph1, aph2, aph3, vh0, vh1);
                mma_bf16(oacc[2 * dp],     aph0, aph1, aph2, aph3, vl0, vl1);
                mma_bf16(oacc[2 * dp],     apl0, apl1, apl2, apl3, vh0, vh1);
                mma_bf16(oacc[2 * dp + 1], aph0, aph1, aph2, aph3, vh2, vh3);
                mma_bf16(oacc[2 * dp + 1], aph0, aph1, aph2, aph3, vl2, vl3);
                mma_bf16(oacc[2 * dp + 1], apl0, apl1, apl2, apl3, vh2, vh3);
            }
        }
        pb ^= 1;
    }

    // ---- finalize ----
    const float inv0 = 1.f / lrun0, inv1 = 1.f / lrun1;
    float* o0 = O + (bS + qb + g) * D_ + h * DK_;
    float* o1 = o0 + 8 * D_;
    #pragma unroll
    for (int dn = 0; dn < 8; dn++) {
        int c = dn * 8 + 2 * tig;
        *reinterpret_cast<float2*>(o0 + c) =
            make_float2(oacc[dn].x * inv0, oacc[dn].y * inv0);
        *reinterpret_cast<float2*>(o1 + c) =
            make_float2(oacc[dn].z * inv1, oacc[dn].w * inv1);
    }
}

// ---------------------------------------------------------------------------
// Launch: 5 kernels, graph-capturable, no allocations / syncs.
// ---------------------------------------------------------------------------
extern "C" void kernel_launch(void* const* d_in, const int* in_sizes, int n_in,
                              void* d_out, int out_size)
{
    const float* q    = (const float*)d_in[0];
    const float* k    = (const float*)d_in[1];
    const float* v    = (const float*)d_in[2];
    const int*   mask = (const int*)  d_in[3];
    const float* w_q  = (const float*)d_in[4];
    const float* w_k  = (const float*)d_in[5];
    const float* w_v  = (const float*)d_in[6];
    const float* w_o  = (const float*)d_in[7];
    float* out = (float*)d_out;

    uint32_t *qh, *ql, *kh, *kl, *vh, *vl;
    float* ga;
    cudaGetSymbolAddress((void**)&qh, g_Qh);
    cudaGetSymbolAddress((void**)&ql, g_Ql);
    cudaGetSymbolAddress((void**)&kh, g_Kh);
    cudaGetSymbolAddress((void**)&kl, g_Kl);
    cudaGetSymbolAddress((void**)&vh, g_Vh);
    cudaGetSymbolAddress((void**)&vl, g_Vl);
    cudaGetSymbolAddress((void**)&ga, g_A);

    const int M = B_ * S_;                 // 8192
    dim3 gemm_grid(D_ / 128, M / 128);     // (8, 64)

    const int gemm_smem = 4 * BUF * (int)sizeof(uint32_t);   // 73728 B
    cudaFuncSetAttribute(gemm_bf16_kernel<true>,
                         cudaFuncAttributeMaxDynamicSharedMemorySize, gemm_smem);
    cudaFuncSetAttribute(gemm_bf16_kernel<false>,
                         cudaFuncAttributeMaxDynamicSharedMemorySize, gemm_smem);

    gemm_bf16_kernel<true><<<gemm_grid, 256, gemm_smem>>>(
        q, w_q, nullptr, qh, ql, M, D_);
    gemm_bf16_kernel<true><<<gemm_grid, 256, gemm_smem>>>(
        k, w_k, nullptr, kh, kl, M, D_);
    gemm_bf16_kernel<true><<<gemm_grid, 256, gemm_smem>>>(
        v, w_v, nullptr, vh, vl, M, D_);

    const int attn_smem = ATOT * (int)sizeof(uint32_t);      // 110592 B
    cudaFuncSetAttribute(attn_mma_kernel,
                         cudaFuncAttributeMaxDynamicSharedMemorySize, attn_smem);
    dim3 attn_grid(S_ / 128, B_ * H_);     // (16, 64)
    attn_mma_kernel<<<attn_grid, 256, attn_smem>>>(
        qh, ql, kh, kl, vh, vl, mask, ga);

    gemm_bf16_kernel<false><<<gemm_grid, 256, gemm_smem>>>(
        ga, w_o, out, nullptr, nullptr, M, D_);
}

// round 15
// speedup vs baseline: 4.1808x; 1.0154x over previous
#include <cuda_runtime.h>
#include <cuda_bf16.h>
#include <cstdint>

#define B_  4
#define S_  2048
#define D_  1024
#define H_  16
#define DK_ 64
#define DP_ 512   // D/2 packed u32 per row

// Scratch (no cudaMalloc; __device__ globals), all bf16 hi/lo packed u32.
__device__ uint32_t g_Xqh[(size_t)B_ * S_ * DP_];   // split input q
__device__ uint32_t g_Xql[(size_t)B_ * S_ * DP_];
__device__ uint32_t g_Xkh[(size_t)B_ * S_ * DP_];   // split input k
__device__ uint32_t g_Xkl[(size_t)B_ * S_ * DP_];
__device__ uint32_t g_Xvh[(size_t)B_ * S_ * DP_];   // split input v
__device__ uint32_t g_Xvl[(size_t)B_ * S_ * DP_];
__device__ uint32_t g_Wqh[(size_t)D_ * DP_];        // split weights
__device__ uint32_t g_Wql[(size_t)D_ * DP_];
__device__ uint32_t g_Wkh[(size_t)D_ * DP_];
__device__ uint32_t g_Wkl[(size_t)D_ * DP_];
__device__ uint32_t g_Wvh[(size_t)D_ * DP_];
__device__ uint32_t g_Wvl[(size_t)D_ * DP_];
__device__ uint32_t g_Woh[(size_t)D_ * DP_];
__device__ uint32_t g_Wol[(size_t)D_ * DP_];
__device__ uint32_t g_Qh[(size_t)B_ * S_ * DP_];    // projected Q/K/V
__device__ uint32_t g_Ql[(size_t)B_ * S_ * DP_];
__device__ uint32_t g_Kh[(size_t)B_ * S_ * DP_];
__device__ uint32_t g_Kl[(size_t)B_ * S_ * DP_];
__device__ uint32_t g_Vh[(size_t)B_ * S_ * DP_];
__device__ uint32_t g_Vl[(size_t)B_ * S_ * DP_];
__device__ uint32_t g_Oh[(size_t)B_ * S_ * DP_];    // attn out split
__device__ uint32_t g_Ol[(size_t)B_ * S_ * DP_];

// ===========================================================================
// Common helpers
// ===========================================================================
__device__ __forceinline__ uint32_t smem_u32(const void* p)
{
    uint32_t a;
    asm("{ .reg .u64 t; cvta.to.shared.u64 t, %1; cvt.u32.u64 %0, t; }"
        : "=r"(a) : "l"(p));
    return a;
}

__device__ __forceinline__ uint32_t pack_bf16(__nv_bfloat16 a, __nv_bfloat16 b)
{
    return (uint32_t)__bfloat16_as_ushort(a) |
           ((uint32_t)__bfloat16_as_ushort(b) << 16);
}

__device__ __forceinline__ void mma_bf16(float4& c,
    uint32_t a0, uint32_t a1, uint32_t a2, uint32_t a3,
    uint32_t b0, uint32_t b1)
{
    asm volatile(
        "mma.sync.aligned.m16n8k16.row.col.f32.bf16.bf16.f32 "
        "{%0,%1,%2,%3}, {%4,%5,%6,%7}, {%8,%9}, {%0,%1,%2,%3};"
        : "+f"(c.x), "+f"(c.y), "+f"(c.z), "+f"(c.w)
        : "r"(a0), "r"(a1), "r"(a2), "r"(a3), "r"(b0), "r"(b1));
}

__device__ __forceinline__ void ldm_x4(uint32_t& r0, uint32_t& r1,
                                       uint32_t& r2, uint32_t& r3, uint32_t a)
{
    asm volatile(
        "ldmatrix.sync.aligned.m8n8.x4.shared.b16 {%0,%1,%2,%3}, [%4];"
        : "=r"(r0), "=r"(r1), "=r"(r2), "=r"(r3) : "r"(a));
}

__device__ __forceinline__ void ldm_x4_t(uint32_t& r0, uint32_t& r1,
                                         uint32_t& r2, uint32_t& r3, uint32_t a)
{
    asm volatile(
        "ldmatrix.sync.aligned.m8n8.x4.trans.shared.b16 {%0,%1,%2,%3}, [%4];"
        : "=r"(r0), "=r"(r1), "=r"(r2), "=r"(r3) : "r"(a));
}

__device__ __forceinline__ void cpa16(uint32_t dst, const void* src)
{
    asm volatile("cp.async.ca.shared.global [%0], [%1], 16;"
                 :: "r"(dst), "l"(src) : "memory");
}

// Fast exp on the FMA pipe (no MUFU).
__device__ __forceinline__ float fexp(float x)
{
    float t = fmaxf(x * 1.4426950408889634f, -126.0f);
    float z = t + 12582912.0f;
    int  ei = __float_as_int(z) - 0x4B400000;
    float f = t - (z - 12582912.0f);
    float p = fmaf(0.0013333558f, f, 0.0096181291f);
    p = fmaf(p, f, 0.0555041087f);
    p = fmaf(p, f, 0.2402265069f);
    p = fmaf(p, f, 0.6931471806f);
    p = fmaf(p, f, 1.0f);
    return __int_as_float(__float_as_int(p) + (ei << 23));
}

// ===========================================================================
// Split kernel: fp32 -> packed bf16 hi/lo (Dekker), memory-bound.
// ===========================================================================
__global__ void __launch_bounds__(256)
split_kernel(const float* __restrict__ src, uint32_t* __restrict__ hi,
             uint32_t* __restrict__ lo, int n4)
{
    int i = blockIdx.x * 256 + threadIdx.x;
    if (i >= n4) return;
    float4 v = reinterpret_cast<const float4*>(src)[i];
    __nv_bfloat16 hx = __float2bfloat16(v.x), hy = __float2bfloat16(v.y);
    __nv_bfloat16 hz = __float2bfloat16(v.z), hw = __float2bfloat16(v.w);
    reinterpret_cast<uint2*>(hi)[i] =
        make_uint2(pack_bf16(hx, hy), pack_bf16(hz, hw));
    reinterpret_cast<uint2*>(lo)[i] = make_uint2(
        pack_bf16(__float2bfloat16(v.x - __bfloat162float(hx)),
                  __float2bfloat16(v.y - __bfloat162float(hy))),
        pack_bf16(__float2bfloat16(v.z - __bfloat162float(hz)),
                  __float2bfloat16(v.w - __bfloat162float(hw))));
}

// ===========================================================================
// bf16x3 GEMM on pre-split operands: C = A * B^T.
// BK=32, cp.async double-buffered, ldmatrix frags.
// smem: 2 stages x 4 bufs x 128 rows x 20 u32 (stride 20: 16B-aligned rows,
// 20r mod 32 distinct -> conflict-free ldmatrix). 81920 B -> 2 CTAs/SM.
// ===========================================================================
#define GST2 20
#define GBUF (128 * GST2)          // 2560 u32 per buffer
#define GSTG (4 * GBUF)            // 10240 u32 per stage

__device__ __forceinline__ uint32_t a_off2(int lane)
{
    return (uint32_t)(((lane & 15) * GST2 + (lane >> 4) * 4) * 4);
}
__device__ __forceinline__ uint32_t b_off2(int lane)
{
    return (uint32_t)((((lane & 7) + ((lane >> 4) << 3)) * GST2 +
                       ((lane >> 3) & 1) * 4) * 4);
}

template<bool SPLIT>
__global__ void __launch_bounds__(256, 2)
gemm_sp_kernel(const uint32_t* __restrict__ Ahg, const uint32_t* __restrict__ Alg,
               const uint32_t* __restrict__ Bhg, const uint32_t* __restrict__ Blg,
               float* __restrict__ C, uint32_t* __restrict__ Chi,
               uint32_t* __restrict__ Clo, int M, int N)
{
    extern __shared__ uint32_t smu[];
    const uint32_t sb = smem_u32(smu);

    const int tid  = threadIdx.x;
    const int lane = tid & 31;
    const int warp = tid >> 5;
    const int g    = lane >> 2;
    const int tig  = lane & 3;
    const int wm   = (warp >> 2) * 64;
    const int wn   = (warp & 3) * 32;
    const int m0   = blockIdx.y * 128;
    const int n0   = blockIdx.x * 128;
    const uint32_t ao = a_off2(lane);
    const uint32_t bo = b_off2(lane);

    // stage one BK=32 chunk (u32 col range [kc, kc+16)) into stage ss
    auto stage = [&](int kc, int ss) {
        const uint32_t tb = sb + (uint32_t)(ss * GSTG) * 4;
        #pragma unroll
        for (int i = 0; i < 8; i++) {
            int idx = tid + i * 256;       // 0..2047
            int bf  = idx >> 9;            // 0 Ah, 1 Al, 2 Bh, 3 Bl
            int rem = idx & 511;
            int r   = rem >> 2;            // 0..127
            int c   = (rem & 3) * 4;       // u32 chunk
            const uint32_t* base =
                (bf == 0) ? Ahg + (size_t)(m0 + r) * DP_ :
                (bf == 1) ? Alg + (size_t)(m0 + r) * DP_ :
                (bf == 2) ? Bhg + (size_t)(n0 + r) * DP_ :
                            Blg + (size_t)(n0 + r) * DP_;
            cpa16(tb + (uint32_t)(bf * GBUF + r * GST2 + c) * 4,
                  base + kc + c);
        }
    };

    float4 acc[4][4];
    #pragma unroll
    for (int i = 0; i < 4; i++)
        #pragma unroll
        for (int j = 0; j < 4; j++) acc[i][j] = make_float4(0.f, 0.f, 0.f, 0.f);

    stage(0, 0);
    asm volatile("cp.async.commit_group;" ::: "memory");
    int ps = 0;

    for (int kc = 0; kc < DP_; kc += 16) {       // 32 iterations
        __syncthreads();
        const bool more = (kc + 16 < DP_);
        if (more) {
            stage(kc + 16, ps ^ 1);
            asm volatile("cp.async.commit_group;" ::: "memory");
            asm volatile("cp.async.wait_group 1;" ::: "memory");
        } else {
            asm volatile("cp.async.wait_group 0;" ::: "memory");
        }
        __syncthreads();

        const uint32_t tb  = sb + (uint32_t)(ps * GSTG) * 4;
        const uint32_t sAh = tb;
        const uint32_t sAl = tb + (uint32_t)GBUF * 4;
        const uint32_t sBh = tb + (uint32_t)(2 * GBUF) * 4;
        const uint32_t sBl = tb + (uint32_t)(3 * GBUF) * 4;

        #pragma unroll
        for (int ks = 0; ks < 2; ks++) {
            uint32_t bh[4][2], bl[4][2];
            #pragma unroll
            for (int tp = 0; tp < 2; tp++) {
                uint32_t ba = (uint32_t)(((wn + tp * 16) * GST2 + ks * 8) * 4) + bo;
                ldm_x4(bh[2 * tp][0], bh[2 * tp][1],
                       bh[2 * tp + 1][0], bh[2 * tp + 1][1], sBh + ba);
                ldm_x4(bl[2 * tp][0], bl[2 * tp][1],
                       bl[2 * tp + 1][0], bl[2 * tp + 1][1], sBl + ba);
            }
            #pragma unroll
            for (int tm = 0; tm < 4; tm++) {
                uint32_t aa = (uint32_t)(((wm + tm * 16) * GST2 + ks * 8) * 4) + ao;
                uint32_t ah0, ah1, ah2, ah3, al0, al1, al2, al3;
                ldm_x4(ah0, ah1, ah2, ah3, sAh + aa);
                ldm_x4(al0, al1, al2, al3, sAl + aa);
                #pragma unroll
                for (int tn = 0; tn < 4; tn++) {
                    mma_bf16(acc[tm][tn], ah0, ah1, ah2, ah3,
                             bh[tn][0], bh[tn][1]);
                    mma_bf16(acc[tm][tn], ah0, ah1, ah2, ah3,
                             bl[tn][0], bl[tn][1]);
                    mma_bf16(acc[tm][tn], al0, al1, al2, al3,
                             bh[tn][0], bh[tn][1]);
                }
            }
        }
        ps ^= 1;
    }

    #pragma unroll
    for (int tm = 0; tm < 4; tm++) {
        #pragma unroll
        for (int tn = 0; tn < 4; tn++) {
            int row = m0 + wm + tm * 16 + g;
            int col = n0 + wn + tn * 8 + 2 * tig;
            if (SPLIT) {
                float4 c4v = acc[tm][tn];
                size_t i0 = (size_t)row * DP_ + (col >> 1);
                size_t i1 = (size_t)(row + 8) * DP_ + (col >> 1);
                __nv_bfloat16 hx = __float2bfloat16(c4v.x);
                __nv_bfloat16 hy = __float2bfloat16(c4v.y);
                __nv_bfloat16 hz = __float2bfloat16(c4v.z);
                __nv_bfloat16 hw = __float2bfloat16(c4v.w);
                Chi[i0] = pack_bf16(hx, hy);
                Chi[i1] = pack_bf16(hz, hw);
                Clo[i0] = pack_bf16(
                    __float2bfloat16(c4v.x - __bfloat162float(hx)),
                    __float2bfloat16(c4v.y - __bfloat162float(hy)));
                Clo[i1] = pack_bf16(
                    __float2bfloat16(c4v.z - __bfloat162float(hz)),
                    __float2bfloat16(c4v.w - __bfloat162float(hw)));
            } else {
                *reinterpret_cast<float2*>(C + (size_t)row * N + col) =
                    make_float2(acc[tm][tn].x, acc[tm][tn].y);
                *reinterpret_cast<float2*>(C + (size_t)(row + 8) * N + col) =
                    make_float2(acc[tm][tn].z, acc[tm][tn].w);
            }
        }
    }
}

// ===========================================================================
// bf16x3 mma flash attention (R14 measured 732 us), epilogue now writes
// split hi/lo for the final GEMM. Internals unchanged.
// ===========================================================================
#define AST 36
#define TQH 0
#define TQL 4608
#define TB0 9216
#define TBSZ 9216
#define ATOT 27648

__device__ __forceinline__ uint32_t a_off(int lane)
{
    return (uint32_t)(((lane & 15) * AST + (lane >> 4) * 4) * 4);
}
__device__ __forceinline__ uint32_t b_off(int lane)
{
    return (uint32_t)((((lane & 7) + ((lane >> 4) << 3)) * AST +
                       ((lane >> 3) & 1) * 4) * 4);
}
__device__ __forceinline__ uint32_t v_off(int lane)
{
    return (uint32_t)(((lane & 15) * AST + (lane >> 4) * 4) * 4);
}

__global__ void __launch_bounds__(256, 2)
attn_mma_kernel(const uint32_t* __restrict__ qh, const uint32_t* __restrict__ ql,
                const uint32_t* __restrict__ kh, const uint32_t* __restrict__ kl,
                const uint32_t* __restrict__ vh, const uint32_t* __restrict__ vl,
                const int* __restrict__ mask,
                uint32_t* __restrict__ ohi, uint32_t* __restrict__ olo)
{
    extern __shared__ uint32_t smu[];
    const uint32_t sb = smem_u32(smu);

    const int tid  = threadIdx.x;
    const int lane = tid & 31;
    const int warp = tid >> 5;
    const int g    = lane >> 2;
    const int tig  = lane & 3;
    const int b    = blockIdx.y >> 4;
    const int h    = blockIdx.y & 15;
    const int q0   = blockIdx.x * 128;
    const int qb   = q0 + warp * 16;
    const uint32_t ao = a_off(lane);
    const uint32_t bo = b_off(lane);
    const uint32_t vo = v_off(lane);
    const size_t   bS = (size_t)b * S_;

    #pragma unroll
    for (int i = 0; i < 8; i++) {
        int idx = tid + i * 256;
        int hl = idx >> 10;
        int rem = idx & 1023;
        int r = rem >> 3, c = rem & 7;
        const uint32_t* src = (hl ? ql : qh) +
            (bS + q0 + r) * DP_ + h * 32 + c * 4;
        uint4 v = *reinterpret_cast<const uint4*>(src);
        *reinterpret_cast<uint4*>(smu + (hl ? TQL : TQH) + r * AST + c * 4) = v;
    }

    auto stage = [&](int kt, int bb) {
        const uint32_t tb = sb + (uint32_t)(TB0 + bb * TBSZ) * 4;
        #pragma unroll
        for (int i = 0; i < 8; i++) {
            int idx = tid + i * 256;
            int tv  = idx >> 10;
            int rem = idx & 1023;
            int hl  = rem >> 9;
            int r   = (rem >> 3) & 63;
            int c   = rem & 7;
            const uint32_t* src = (tv ? (hl ? vl : vh) : (hl ? kl : kh)) +
                (bS + kt + r) * DP_ + h * 32 + c * 4;
            uint32_t dst = tb + (uint32_t)((tv * 2 + hl) * 2304 +
                                           r * AST + c * 4) * 4;
            cpa16(dst, src);
        }
    };

    float4 oacc[8];
    #pragma unroll
    for (int i = 0; i < 8; i++) oacc[i] = make_float4(0.f, 0.f, 0.f, 0.f);
    float mrun0 = -1e30f, mrun1 = -1e30f, lrun0 = 0.f, lrun1 = 0.f;

    stage(0, 0);
    asm volatile("cp.async.commit_group;" ::: "memory");
    int pb = 0;

    for (int kt = 0; kt < S_; kt += 64) {
        __syncthreads();
        const bool more = (kt + 64 < S_);
        if (more) {
            stage(kt + 64, pb ^ 1);
            asm volatile("cp.async.commit_group;" ::: "memory");
            asm volatile("cp.async.wait_group 1;" ::: "memory");
        } else {
            asm volatile("cp.async.wait_group 0;" ::: "memory");
        }
        __syncthreads();

        const uint32_t tb  = sb + (uint32_t)(TB0 + pb * TBSZ) * 4;
        const uint32_t kbh = tb;
        const uint32_t kbl = tb + 2304u * 4;
        const uint32_t vbh = tb + 4608u * 4;
        const uint32_t vbl = tb + 6912u * 4;

        float4 sacc[8];
        #pragma unroll
        for (int j = 0; j < 8; j++) sacc[j] = make_float4(0.f, 0.f, 0.f, 0.f);

        #pragma unroll
        for (int ks = 0; ks < 4; ks++) {
            uint32_t aa = (uint32_t)(((warp * 16) * AST + ks * 8) * 4) + ao;
            uint32_t ah0, ah1, ah2, ah3, al0, al1, al2, al3;
            ldm_x4(ah0, ah1, ah2, ah3, sb + TQH * 4 + aa);
            ldm_x4(al0, al1, al2, al3, sb + TQL * 4 + aa);
            #pragma unroll
            for (int jp = 0; jp < 4; jp++) {
                uint32_t ba = (uint32_t)(((jp * 16) * AST + ks * 8) * 4) + bo;
                uint32_t bh0, bh1, bh2, bh3, bl0, bl1, bl2, bl3;
                ldm_x4(bh0, bh1, bh2, bh3, kbh + ba);
                ldm_x4(bl0, bl1, bl2, bl3, kbl + ba);
                mma_bf16(sacc[2 * jp],     ah0, ah1, ah2, ah3, bh0, bh1);
                mma_bf16(sacc[2 * jp],     ah0, ah1, ah2, ah3, bl0, bl1);
                mma_bf16(sacc[2 * jp],     al0, al1, al2, al3, bh0, bh1);
                mma_bf16(sacc[2 * jp + 1], ah0, ah1, ah2, ah3, bh2, bh3);
                mma_bf16(sacc[2 * jp + 1], ah0, ah1, ah2, ah3, bl2, bl3);
                mma_bf16(sacc[2 * jp + 1], al0, al1, al2, al3, bh2, bh3);
            }
        }

        const size_t mrow0 = (bS + qb + g) * S_ + kt;
        const size_t mrow1 = mrow0 + 8 * S_;
        #pragma unroll
        for (int jn = 0; jn < 8; jn++) {
            int kc = jn * 8 + 2 * tig;
            int2 m0 = *reinterpret_cast<const int2*>(mask + mrow0 + kc);
            int2 m1 = *reinterpret_cast<const int2*>(mask + mrow1 + kc);
            sacc[jn].x = m0.x ? sacc[jn].x * 0.125f : -1e9f;
            sacc[jn].y = m0.y ? sacc[jn].y * 0.125f : -1e9f;
            sacc[jn].z = m1.x ? sacc[jn].z * 0.125f : -1e9f;
            sacc[jn].w = m1.y ? sacc[jn].w * 0.125f : -1e9f;
        }

        float rm0 = -1e30f, rm1 = -1e30f;
        #pragma unroll
        for (int jn = 0; jn < 8; jn++) {
            rm0 = fmaxf(rm0, fmaxf(sacc[jn].x, sacc[jn].y));
            rm1 = fmaxf(rm1, fmaxf(sacc[jn].z, sacc[jn].w));
        }
        rm0 = fmaxf(rm0, __shfl_xor_sync(0xffffffffu, rm0, 1));
        rm0 = fmaxf(rm0, __shfl_xor_sync(0xffffffffu, rm0, 2));
        rm1 = fmaxf(rm1, __shfl_xor_sync(0xffffffffu, rm1, 1));
        rm1 = fmaxf(rm1, __shfl_xor_sync(0xffffffffu, rm1, 2));

        float mnew0 = fmaxf(mrun0, rm0), mnew1 = fmaxf(mrun1, rm1);
        float corr0 = fexp(mrun0 - mnew0), corr1 = fexp(mrun1 - mnew1);
        #pragma unroll
        for (int dn = 0; dn < 8; dn++) {
            oacc[dn].x *= corr0; oacc[dn].y *= corr0;
            oacc[dn].z *= corr1; oacc[dn].w *= corr1;
        }
        float ls0 = 0.f, ls1 = 0.f;
        #pragma unroll
        for (int jn = 0; jn < 8; jn++) {
            sacc[jn].x = fexp(sacc[jn].x - mnew0);
            sacc[jn].y = fexp(sacc[jn].y - mnew0);
            sacc[jn].z = fexp(sacc[jn].z - mnew1);
            sacc[jn].w = fexp(sacc[jn].w - mnew1);
            ls0 += sacc[jn].x + sacc[jn].y;
            ls1 += sacc[jn].z + sacc[jn].w;
        }
        ls0 += __shfl_xor_sync(0xffffffffu, ls0, 1);
        ls0 += __shfl_xor_sync(0xffffffffu, ls0, 2);
        ls1 += __shfl_xor_sync(0xffffffffu, ls1, 1);
        ls1 += __shfl_xor_sync(0xffffffffu, ls1, 2);
        lrun0 = lrun0 * corr0 + ls0;
        lrun1 = lrun1 * corr1 + ls1;
        mrun0 = mnew0; mrun1 = mnew1;

        #pragma unroll
        for (int t = 0; t < 4; t++) {
            const float4 p0 = sacc[2 * t], p1 = sacc[2 * t + 1];
            __nv_bfloat16 h0x = __float2bfloat16(p0.x), h0y = __float2bfloat16(p0.y);
            __nv_bfloat16 h0z = __float2bfloat16(p0.z), h0w = __float2bfloat16(p0.w);
            __nv_bfloat16 h1x = __float2bfloat16(p1.x), h1y = __float2bfloat16(p1.y);
            __nv_bfloat16 h1z = __float2bfloat16(p1.z), h1w = __float2bfloat16(p1.w);
            uint32_t aph0 = pack_bf16(h0x, h0y);
            uint32_t aph1 = pack_bf16(h0z, h0w);
            uint32_t aph2 = pack_bf16(h1x, h1y);
            uint32_t aph3 = pack_bf16(h1z, h1w);
            uint32_t apl0 = pack_bf16(
                __float2bfloat16(p0.x - __bfloat162float(h0x)),
                __float2bfloat16(p0.y - __bfloat162float(h0y)));
            uint32_t apl1 = pack_bf16(
                __float2bfloat16(p0.z - __bfloat162float(h0z)),
                __float2bfloat16(p0.w - __bfloat162float(h0w)));
            uint32_t apl2 = pack_bf16(
                __float2bfloat16(p1.x - __bfloat162float(h1x)),
                __float2bfloat16(p1.y - __bfloat162float(h1y)));
            uint32_t apl3 = pack_bf16(
                __float2bfloat16(p1.z - __bfloat162float(h1z)),
                __float2bfloat16(p1.w - __bfloat162float(h1w)));
            #pragma unroll
            for (int dp = 0; dp < 4; dp++) {
                uint32_t ba = (uint32_t)(((t * 16) * AST + dp * 8) * 4) + vo;
                uint32_t vh0, vh1, vh2, vh3, vl0, vl1, vl2, vl3;
                ldm_x4_t(vh0, vh1, vh2, vh3, vbh + ba);
                ldm_x4_t(vl0, vl1, vl2, vl3, vbl + ba);
                mma_bf16(oacc[2 * dp],     aph0, aph1, aph2, aph3, vh0, vh1);
                mma_bf16(oacc[2 * dp],     aph0, aph1, aph2, aph3, vl0, vl1);
                mma_bf16(oacc[2 * dp],     apl0, apl1, apl2, apl3, vh0, vh1);
                mma_bf16(oacc[2 * dp + 1], aph0, aph1, aph2, aph3, vh2, vh3);
                mma_bf16(oacc[2 * dp + 1], aph0, aph1, aph2, aph3, vl2, vl3);
                mma_bf16(oacc[2 * dp + 1], apl0, apl1, apl2, apl3, vh2, vh3);
            }
        }
        pb ^= 1;
    }

    // ---- finalize: normalize and write split hi/lo ----
    const float inv0 = 1.f / lrun0, inv1 = 1.f / lrun1;
    const size_t r0 = (bS + qb + g) * DP_ + h * 32;
    const size_t r1 = r0 + 8 * DP_;
    #pragma unroll
    for (int dn = 0; dn < 8; dn++) {
        size_t i0 = r0 + dn * 4 + tig;
        size_t i1 = r1 + dn * 4 + tig;
        float x0 = oacc[dn].x * inv0, y0 = oacc[dn].y * inv0;
        float x1 = oacc[dn].z * inv1, y1 = oacc[dn].w * inv1;
        __nv_bfloat16 hx0 = __float2bfloat16(x0), hy0 = __float2bfloat16(y0);
        __nv_bfloat16 hx1 = __float2bfloat16(x1), hy1 = __float2bfloat16(y1);
        ohi[i0] = pack_bf16(hx0, hy0);
        ohi[i1] = pack_bf16(hx1, hy1);
        olo[i0] = pack_bf16(__float2bfloat16(x0 - __bfloat162float(hx0)),
                            __float2bfloat16(y0 - __bfloat162float(hy0)));
        olo[i1] = pack_bf16(__float2bfloat16(x1 - __bfloat162float(hx1)),
                            __float2bfloat16(y1 - __bfloat162float(hy1)));
    }
}

// ---------------------------------------------------------------------------
// Launch: graph-capturable, no allocations / syncs.
// ---------------------------------------------------------------------------
extern "C" void kernel_launch(void* const* d_in, const int* in_sizes, int n_in,
                              void* d_out, int out_size)
{
    const float* q    = (const float*)d_in[0];
    const float* k    = (const float*)d_in[1];
    const float* v    = (const float*)d_in[2];
    const int*   mask = (const int*)  d_in[3];
    const float* w_q  = (const float*)d_in[4];
    const float* w_k  = (const float*)d_in[5];
    const float* w_v  = (const float*)d_in[6];
    const float* w_o  = (const float*)d_in[7];
    float* out = (float*)d_out;

    uint32_t *xqh, *xql, *xkh, *xkl, *xvh, *xvl;
    uint32_t *wqh, *wql, *wkh, *wkl, *wvh, *wvl, *woh, *wol;
    uint32_t *qh, *ql, *kh, *kl, *vh, *vl, *ohv, *olv;
    cudaGetSymbolAddress((void**)&xqh, g_Xqh); cudaGetSymbolAddress((void**)&xql, g_Xql);
    cudaGetSymbolAddress((void**)&xkh, g_Xkh); cudaGetSymbolAddress((void**)&xkl, g_Xkl);
    cudaGetSymbolAddress((void**)&xvh, g_Xvh); cudaGetSymbolAddress((void**)&xvl, g_Xvl);
    cudaGetSymbolAddress((void**)&wqh, g_Wqh); cudaGetSymbolAddress((void**)&wql, g_Wql);
    cudaGetSymbolAddress((void**)&wkh, g_Wkh); cudaGetSymbolAddress((void**)&wkl, g_Wkl);
    cudaGetSymbolAddress((void**)&wvh, g_Wvh); cudaGetSymbolAddress((void**)&wvl, g_Wvl);
    cudaGetSymbolAddress((void**)&woh, g_Woh); cudaGetSymbolAddress((void**)&wol, g_Wol);
    cudaGetSymbolAddress((void**)&qh, g_Qh);   cudaGetSymbolAddress((void**)&ql, g_Ql);
    cudaGetSymbolAddress((void**)&kh, g_Kh);   cudaGetSymbolAddress((void**)&kl, g_Kl);
    cudaGetSymbolAddress((void**)&vh, g_Vh);   cudaGetSymbolAddress((void**)&vl, g_Vl);
    cudaGetSymbolAddress((void**)&ohv, g_Oh);  cudaGetSymbolAddress((void**)&olv, g_Ol);

    const int M = B_ * S_;                 // 8192
    const int n4in = M * D_ / 4;           // input elems / 4
    const int n4w  = D_ * D_ / 4;

    split_kernel<<<(n4in + 255) / 256, 256>>>(q, xqh, xql, n4in);
    split_kernel<<<(n4in + 255) / 256, 256>>>(k, xkh, xkl, n4in);
    split_kernel<<<(n4in + 255) / 256, 256>>>(v, xvh, xvl, n4in);
    split_kernel<<<(n4w + 255) / 256, 256>>>(w_q, wqh, wql, n4w);
    split_kernel<<<(n4w + 255) / 256, 256>>>(w_k, wkh, wkl, n4w);
    split_kernel<<<(n4w + 255) / 256, 256>>>(w_v, wvh, wvl, n4w);
    split_kernel<<<(n4w + 255) / 256, 256>>>(w_o, woh, wol, n4w);

    dim3 gemm_grid(D_ / 128, M / 128);     // (8, 64)
    const int gemm_smem = 2 * GSTG * (int)sizeof(uint32_t);  // 81920 B
    cudaFuncSetAttribute(gemm_sp_kernel<true>,
                         cudaFuncAttributeMaxDynamicSharedMemorySize, gemm_smem);
    cudaFuncSetAttribute(gemm_sp_kernel<false>,
                         cudaFuncAttributeMaxDynamicSharedMemorySize, gemm_smem);

    gemm_sp_kernel<true><<<gemm_grid, 256, gemm_smem>>>(
        xqh, xql, wqh, wql, nullptr, qh, ql, M, D_);
    gemm_sp_kernel<true><<<gemm_grid, 256, gemm_smem>>>(
        xkh, xkl, wkh, wkl, nullptr, kh, kl, M, D_);
    gemm_sp_kernel<true><<<gemm_grid, 256, gemm_smem>>>(
        xvh, xvl, wvh, wvl, nullptr, vh, vl, M, D_);

    const int attn_smem = ATOT * (int)sizeof(uint32_t);      // 110592 B
    cudaFuncSetAttribute(attn_mma_kernel,
                         cudaFuncAttributeMaxDynamicSharedMemorySize, attn_smem);
    dim3 attn_grid(S_ / 128, B_ * H_);     // (16, 64)
    attn_mma_kernel<<<attn_grid, 256, attn_smem>>>(
        qh, ql, kh, kl, vh, vl, mask, ohv, olv);

    gemm_sp_kernel<false><<<gemm_grid, 256, gemm_smem>>>(
        ohv, olv, woh, wol, out, nullptr, nullptr, M, D_);
}